// round 12
// baseline (speedup 1.0000x reference)
#include <cuda_runtime.h>
#include <cuda_bf16.h>

// Problem constants
#define NN 50000
#define EE 800000

// ---------------- scratch (device globals; no allocation allowed) -----------
__device__ float g_h  [(long long)NN * 128];
__device__ float g_s  [(long long)NN * 128];
__device__ float g_agg[(long long)NN * 128];
__device__ float g_m  [(long long)NN * 256];
__device__ float g_gi [(long long)NN * 384];
__device__ float g_gh [(long long)NN * 384];
__device__ float g_inv[NN];
__device__ int   g_cnt[NN];
__device__ int   g_start[NN + 1];
__device__ int   g_head[NN];
__device__ int   g_csr_row[EE];
__device__ float g_csr_ea[EE];

#define BUF_H   0
#define BUF_S   1
#define BUF_AGG 2
#define BUF_M   3
#define BUF_GI  4
#define BUF_GH  5

__device__ __forceinline__ float* buf(int id) {
    switch (id) {
        case BUF_H:   return g_h;
        case BUF_S:   return g_s;
        case BUF_AGG: return g_agg;
        case BUF_M:   return g_m;
        case BUF_GI:  return g_gi;
        case BUF_GH:  return g_gh;
    }
    return nullptr;
}

// ---------------- degree / CSR build ----------------------------------------
__global__ void zero_cnt_kernel() {
    int i = blockIdx.x * blockDim.x + threadIdx.x;
    if (i < NN) g_cnt[i] = 0;
}

// edge_index is int32 (JAX x64 disabled)
__global__ void count_kernel(const int* __restrict__ ei) {
    int e = blockIdx.x * blockDim.x + threadIdx.x;
    if (e < EE) {
        unsigned c = (unsigned)ei[EE + e];
        if (c < NN) atomicAdd(&g_cnt[c], 1);
    }
}

// Single-block exclusive scan over g_cnt -> g_start, g_head, g_inv.
__global__ void scan_kernel() {
    __shared__ int ssum[1024];
    const int CH = (NN + 1023) / 1024;   // 49
    int t = threadIdx.x;
    int beg = t * CH;
    int end = beg + CH; if (end > NN) end = NN;
    int s = 0;
    for (int i = beg; i < end; i++) s += g_cnt[i];
    ssum[t] = s;
    __syncthreads();
    for (int off = 1; off < 1024; off <<= 1) {
        int v = (t >= off) ? ssum[t - off] : 0;
        __syncthreads();
        ssum[t] += v;
        __syncthreads();
    }
    int run = ssum[t] - s;   // exclusive prefix for this chunk
    for (int i = beg; i < end; i++) {
        int c = g_cnt[i];
        g_start[i] = run;
        g_head[i]  = run;
        g_inv[i]   = 1.0f / (float)(c > 0 ? c : 1);
        run += c;
    }
    if (t == 1023) g_start[NN] = ssum[1023];
}

__global__ void fill_kernel(const int* __restrict__ ei,
                            const float* __restrict__ ea) {
    int e = blockIdx.x * blockDim.x + threadIdx.x;
    if (e >= EE) return;
    unsigned r = (unsigned)ei[e];
    unsigned c = (unsigned)ei[EE + e];
    if (c < NN) {
        int p = atomicAdd(&g_head[c], 1);
        g_csr_row[p] = (r < NN) ? (int)r : 0;
        g_csr_ea[p]  = ea[e];
    }
}

// ---------------- node-parallel aggregation (no atomics) --------------------
__global__ void agg_kernel() {
    int gid  = blockIdx.x * blockDim.x + threadIdx.x;
    int n    = gid >> 5;
    int lane = gid & 31;
    if (n >= NN) return;
    int beg = g_start[n];
    int end = g_start[n + 1];
    float4 acc = make_float4(0.f, 0.f, 0.f, 0.f);
    int e = beg;
    for (; e + 1 < end; e += 2) {
        int   r0 = g_csr_row[e];
        int   r1 = g_csr_row[e + 1];
        float a0 = g_csr_ea[e];
        float a1 = g_csr_ea[e + 1];
        float4 v0 = ((const float4*)(g_s + (long long)r0 * 128))[lane];
        float4 v1 = ((const float4*)(g_s + (long long)r1 * 128))[lane];
        acc.x += v0.x * a0 + v1.x * a1;
        acc.y += v0.y * a0 + v1.y * a1;
        acc.z += v0.z * a0 + v1.z * a1;
        acc.w += v0.w * a0 + v1.w * a1;
    }
    if (e < end) {
        int   r0 = g_csr_row[e];
        float a0 = g_csr_ea[e];
        float4 v0 = ((const float4*)(g_s + (long long)r0 * 128))[lane];
        acc.x += v0.x * a0; acc.y += v0.y * a0;
        acc.z += v0.z * a0; acc.w += v0.w * a0;
    }
    float iv = g_inv[n];
    acc.x *= iv; acc.y *= iv; acc.z *= iv; acc.w *= iv;
    ((float4*)(g_agg + (long long)n * 128))[lane] = acc;
}

// ---------------- SGEMM: double-buffered, FFMA2, duplicated-A smem ----------
// Output set selected per block: blockIdx.y < splitY -> (W, bias, Cid, Nc, act),
// else -> (W2, bias2, C2id, Nc2, act2) with yy = blockIdx.y - splitY.
// A = concat(A0[K0], A1[K1]) shared by both sets. BM=BN=128, BK=16, 256 thr.
__global__ __launch_bounds__(256)
void gemm_kernel(const float* __restrict__ A0p, int A0id, int K0,
                 int A1id, int K1,
                 const float* __restrict__ W,  const float* __restrict__ bias,
                 int Cid, int Nc, int act,
                 float* __restrict__ Cp, int M, int splitY,
                 const float* __restrict__ W2, const float* __restrict__ bias2,
                 int C2id, int Nc2, int act2) {
    const int BK = 16;
    __shared__ float As2[2][BK][264];   // duplicated: [k][2m],[k][2m+1] = A[m][k]
    __shared__ float Bs [2][BK][132];

    const float* A0 = (A0id >= 0) ? buf(A0id) : A0p;
    const float* A1 = (A1id >= 0) ? buf(A1id) : nullptr;

    int yy = blockIdx.y;
    const float* Wp; const float* bp_; float* C; int NcS, actS;
    if ((int)blockIdx.y < splitY) {
        Wp = W;  bp_ = bias;  C = (Cid >= 0) ? buf(Cid) : Cp; NcS = Nc;  actS = act;
    } else {
        yy = blockIdx.y - splitY;
        Wp = W2; bp_ = bias2; C = buf(C2id);                  NcS = Nc2; actS = act2;
    }

    const int K  = K0 + K1;
    const int m0 = blockIdx.x * 128;
    const int n0 = yy * 128;
    const int t  = threadIdx.x;
    const int ty = t >> 4;          // 0..15
    const int tx = t & 15;          // 0..15

    unsigned long long acc[8][4];
#pragma unroll
    for (int i = 0; i < 8; i++)
#pragma unroll
        for (int jp = 0; jp < 4; jp++) acc[i][jp] = 0ULL;

    float4 pa[2], pb[2];

    auto load_tiles = [&](int k0) {
#pragma unroll
        for (int q = 0; q < 2; q++) {
            int idx = t + q * 256;          // [0,512)
            int row = idx >> 2;             // 0..127
            int kc  = (idx & 3) * 4;        // 0,4,8,12
            int grow = m0 + row;
            float4 v = make_float4(0.f, 0.f, 0.f, 0.f);
            if (grow < M) {
                int kg = k0 + kc;
                if (kg < K0) v = *(const float4*)(A0 + (long long)grow * K0 + kg);
                else         v = *(const float4*)(A1 + (long long)grow * K1 + (kg - K0));
            }
            pa[q] = v;
            int kr = idx >> 5;              // 0..15
            int nc = (idx & 31) * 4;        // 0..124
            pb[q] = *(const float4*)(Wp + (long long)(k0 + kr) * NcS + n0 + nc);
        }
    };
    auto store_tiles = [&](int sbuf) {
#pragma unroll
        for (int q = 0; q < 2; q++) {
            int idx = t + q * 256;
            int row = idx >> 2;
            int kc  = (idx & 3) * 4;
            // duplicated stores: (v,v) pairs, STS.64 each
            *(float2*)&As2[sbuf][kc + 0][2 * row] = make_float2(pa[q].x, pa[q].x);
            *(float2*)&As2[sbuf][kc + 1][2 * row] = make_float2(pa[q].y, pa[q].y);
            *(float2*)&As2[sbuf][kc + 2][2 * row] = make_float2(pa[q].z, pa[q].z);
            *(float2*)&As2[sbuf][kc + 3][2 * row] = make_float2(pa[q].w, pa[q].w);
            int kr = idx >> 5;
            int nc = (idx & 31) * 4;
            *(float4*)&Bs[sbuf][kr][nc] = pb[q];
        }
    };

    const int niter = K / BK;
    load_tiles(0);
    store_tiles(0);
    __syncthreads();
    int cur = 0;

    for (int it = 0; it < niter; it++) {
        if (it + 1 < niter) load_tiles((it + 1) * BK);

#pragma unroll
        for (int kk = 0; kk < BK; kk++) {
            // pre-splatted A pairs: each ull = (a, a)
            ulonglong2 aq0 = *(const ulonglong2*)&As2[cur][kk][ty * 16];
            ulonglong2 aq1 = *(const ulonglong2*)&As2[cur][kk][ty * 16 + 4];
            ulonglong2 aq2 = *(const ulonglong2*)&As2[cur][kk][ty * 16 + 8];
            ulonglong2 aq3 = *(const ulonglong2*)&As2[cur][kk][ty * 16 + 12];
            // B pairs: each ull = (b_j, b_{j+1})
            ulonglong2 bq0 = *(const ulonglong2*)&Bs[cur][kk][tx * 8];
            ulonglong2 bq1 = *(const ulonglong2*)&Bs[cur][kk][tx * 8 + 4];
            unsigned long long a[8] = {aq0.x, aq0.y, aq1.x, aq1.y,
                                       aq2.x, aq2.y, aq3.x, aq3.y};
            unsigned long long b[4] = {bq0.x, bq0.y, bq1.x, bq1.y};
#pragma unroll
            for (int i = 0; i < 8; i++)
#pragma unroll
                for (int jp = 0; jp < 4; jp++) {
                    asm("fma.rn.f32x2 %0, %1, %2, %0;"
                        : "+l"(acc[i][jp]) : "l"(a[i]), "l"(b[jp]));
                }
        }

        if (it + 1 < niter) {
            __syncthreads();
            store_tiles(cur ^ 1);
            cur ^= 1;
            __syncthreads();
        }
    }

    // --- epilogue: unpack + bias + activation + store (float4)
#pragma unroll
    for (int i = 0; i < 8; i++) {
        int grow = m0 + ty * 8 + i;
        if (grow >= M) continue;
        float c[8];
#pragma unroll
        for (int jp = 0; jp < 4; jp++) {
            asm("mov.b64 {%0,%1}, %2;"
                : "=f"(c[2 * jp]), "=f"(c[2 * jp + 1]) : "l"(acc[i][jp]));
        }
#pragma unroll
        for (int j = 0; j < 8; j += 4) {
            int gc = n0 + tx * 8 + j;
            float4 v;
            v.x = c[j + 0] + bp_[gc + 0];
            v.y = c[j + 1] + bp_[gc + 1];
            v.z = c[j + 2] + bp_[gc + 2];
            v.w = c[j + 3] + bp_[gc + 3];
            if (actS == 1) {
                v.x = v.x > 0.f ? v.x : 0.01f * v.x;
                v.y = v.y > 0.f ? v.y : 0.01f * v.y;
                v.z = v.z > 0.f ? v.z : 0.01f * v.z;
                v.w = v.w > 0.f ? v.w : 0.01f * v.w;
            }
            *(float4*)(C + (long long)grow * NcS + gc) = v;
        }
    }
}

// ---------------- GRU elementwise update (float4) ----------------------------
__global__ void gru_kernel(float* __restrict__ doutp, int writeOut) {
    int idx = blockIdx.x * blockDim.x + threadIdx.x;   // over NN*32
    if (idx >= NN * 32) return;
    int n  = idx >> 5;
    int j4 = idx & 31;
    const float4* gi4 = (const float4*)(g_gi + (long long)n * 384);
    const float4* gh4 = (const float4*)(g_gh + (long long)n * 384);
    float4 ir  = gi4[j4],      hr = gh4[j4];
    float4 iz  = gi4[32 + j4], hz = gh4[32 + j4];
    float4 inn = gi4[64 + j4], hn = gh4[64 + j4];
    float4 h   = ((const float4*)(g_h + (long long)n * 128))[j4];
    float4 o;
    {
        float r = 1.f / (1.f + __expf(-(ir.x + hr.x)));
        float z = 1.f / (1.f + __expf(-(iz.x + hz.x)));
        float nv = tanhf(inn.x + r * hn.x);
        o.x = (1.f - z) * nv + z * h.x;
    }
    {
        float r = 1.f / (1.f + __expf(-(ir.y + hr.y)));
        float z = 1.f / (1.f + __expf(-(iz.y + hz.y)));
        float nv = tanhf(inn.y + r * hn.y);
        o.y = (1.f - z) * nv + z * h.y;
    }
    {
        float r = 1.f / (1.f + __expf(-(ir.z + hr.z)));
        float z = 1.f / (1.f + __expf(-(iz.z + hz.z)));
        float nv = tanhf(inn.z + r * hn.z);
        o.z = (1.f - z) * nv + z * h.z;
    }
    {
        float r = 1.f / (1.f + __expf(-(ir.w + hr.w)));
        float z = 1.f / (1.f + __expf(-(iz.w + hz.w)));
        float nv = tanhf(inn.w + r * hn.w);
        o.w = (1.f - z) * nv + z * h.w;
    }
    if (writeOut) ((float4*)doutp)[idx] = o;
    else          ((float4*)g_h)[idx]  = o;
}

// ---------------- launch -----------------------------------------------------
extern "C" void kernel_launch(void* const* d_in, const int* in_sizes, int n_in,
                              void* d_out, int out_size) {
    const float* x  = (const float*)d_in[0];
    const int*   ei = (const int*)d_in[1];     // int32 (JAX x64 disabled)
    const float* ea = (const float*)d_in[2];
    // d_in[3] = batch (unused)
    const float* W_embed = (const float*)d_in[4];
    const float* b_embed = (const float*)d_in[5];
    const float* W_snd   = (const float*)d_in[6];
    const float* b_snd   = (const float*)d_in[7];
    const float* W_rec   = (const float*)d_in[8];
    const float* b_rec   = (const float*)d_in[9];
    const float* W_ih    = (const float*)d_in[10];
    const float* b_ih    = (const float*)d_in[11];
    const float* W_hh    = (const float*)d_in[12];
    const float* b_hh    = (const float*)d_in[13];

    const int T = 256;
    const int rowBlocks = (NN + 127) / 128;   // 391

    // CSR build (per call, deterministic work)
    zero_cnt_kernel<<<(NN + T - 1) / T, T>>>();
    count_kernel<<<(EE + T - 1) / T, T>>>(ei);
    scan_kernel<<<1, 1024>>>();
    fill_kernel<<<(EE + T - 1) / T, T>>>(ei, ea);

    // embed: h = x @ W_embed + b_embed
    gemm_kernel<<<dim3(rowBlocks, 1), T>>>(x, -1, 64, -1, 0,
                                           W_embed, b_embed, BUF_H, 128, 0,
                                           nullptr, NN, 99,
                                           nullptr, nullptr, BUF_H, 128, 0);

    for (int layer = 0; layer < 3; layer++) {
        // fused: s = leaky(h@W_snd+b) [y=0]  and  gh = h@W_hh+b [y=1..3]
        gemm_kernel<<<dim3(rowBlocks, 4), T>>>(nullptr, BUF_H, 128, -1, 0,
                                               W_snd, b_snd, BUF_S, 128, 1,
                                               nullptr, NN, 1,
                                               W_hh, b_hh, BUF_GH, 384, 0);
        // agg = segment_mean via CSR gather (no atomics)
        agg_kernel<<<(NN * 32 + T - 1) / T, T>>>();
        // m = leaky_relu([agg, h] @ W_rec + b_rec)
        gemm_kernel<<<dim3(rowBlocks, 2), T>>>(nullptr, BUF_AGG, 128, BUF_H, 128,
                                               W_rec, b_rec, BUF_M, 256, 1,
                                               nullptr, NN, 99,
                                               nullptr, nullptr, BUF_M, 256, 0);
        // gi = m @ W_ih + b_ih
        gemm_kernel<<<dim3(rowBlocks, 3), T>>>(nullptr, BUF_M, 256, -1, 0,
                                               W_ih, b_ih, BUF_GI, 384, 0,
                                               nullptr, NN, 99,
                                               nullptr, nullptr, BUF_GI, 384, 0);
        // GRU update (last layer writes d_out)
        gru_kernel<<<(NN * 32 + T - 1) / T, T>>>(
            (float*)d_out, layer == 2 ? 1 : 0);
    }
}

// round 13
// speedup vs baseline: 1.2014x; 1.2014x over previous
#include <cuda_runtime.h>
#include <cuda_bf16.h>

// Problem constants
#define NN 50000
#define EE 800000

// ---------------- scratch (device globals; no allocation allowed) -----------
__device__ float g_h  [(long long)NN * 128];
__device__ float g_s  [(long long)NN * 128];
__device__ float g_agg[(long long)NN * 128];
__device__ float g_m  [(long long)NN * 256];
__device__ float g_gi [(long long)NN * 384];
__device__ float g_gh [(long long)NN * 384];
__device__ float g_inv[NN];
__device__ int   g_cnt[NN];
__device__ int   g_start[NN + 1];
__device__ int   g_head[NN];
__device__ int   g_csr_row[EE];
__device__ float g_csr_ea[EE];

#define BUF_H   0
#define BUF_S   1
#define BUF_AGG 2
#define BUF_M   3
#define BUF_GI  4
#define BUF_GH  5

__device__ __forceinline__ float* buf(int id) {
    switch (id) {
        case BUF_H:   return g_h;
        case BUF_S:   return g_s;
        case BUF_AGG: return g_agg;
        case BUF_M:   return g_m;
        case BUF_GI:  return g_gi;
        case BUF_GH:  return g_gh;
    }
    return nullptr;
}

// ---------------- degree / CSR build ----------------------------------------
__global__ void zero_cnt_kernel() {
    int i = blockIdx.x * blockDim.x + threadIdx.x;
    if (i < NN) g_cnt[i] = 0;
}

// edge_index is int32 (JAX x64 disabled)
__global__ void count_kernel(const int* __restrict__ ei) {
    int e = blockIdx.x * blockDim.x + threadIdx.x;
    if (e < EE) {
        unsigned c = (unsigned)ei[EE + e];
        if (c < NN) atomicAdd(&g_cnt[c], 1);
    }
}

// Single-block exclusive scan over g_cnt -> g_start, g_head, g_inv.
__global__ void scan_kernel() {
    __shared__ int ssum[1024];
    const int CH = (NN + 1023) / 1024;   // 49
    int t = threadIdx.x;
    int beg = t * CH;
    int end = beg + CH; if (end > NN) end = NN;
    int s = 0;
    for (int i = beg; i < end; i++) s += g_cnt[i];
    ssum[t] = s;
    __syncthreads();
    for (int off = 1; off < 1024; off <<= 1) {
        int v = (t >= off) ? ssum[t - off] : 0;
        __syncthreads();
        ssum[t] += v;
        __syncthreads();
    }
    int run = ssum[t] - s;   // exclusive prefix for this chunk
    for (int i = beg; i < end; i++) {
        int c = g_cnt[i];
        g_start[i] = run;
        g_head[i]  = run;
        g_inv[i]   = 1.0f / (float)(c > 0 ? c : 1);
        run += c;
    }
    if (t == 1023) g_start[NN] = ssum[1023];
}

__global__ void fill_kernel(const int* __restrict__ ei,
                            const float* __restrict__ ea) {
    int e = blockIdx.x * blockDim.x + threadIdx.x;
    if (e >= EE) return;
    unsigned r = (unsigned)ei[e];
    unsigned c = (unsigned)ei[EE + e];
    if (c < NN) {
        int p = atomicAdd(&g_head[c], 1);
        g_csr_row[p] = (r < NN) ? (int)r : 0;
        g_csr_ea[p]  = ea[e];
    }
}

// ---------------- node-parallel aggregation (no atomics) --------------------
__global__ void agg_kernel() {
    int gid  = blockIdx.x * blockDim.x + threadIdx.x;
    int n    = gid >> 5;
    int lane = gid & 31;
    if (n >= NN) return;
    int beg = g_start[n];
    int end = g_start[n + 1];
    float4 acc = make_float4(0.f, 0.f, 0.f, 0.f);
    int e = beg;
    for (; e + 1 < end; e += 2) {
        int   r0 = g_csr_row[e];
        int   r1 = g_csr_row[e + 1];
        float a0 = g_csr_ea[e];
        float a1 = g_csr_ea[e + 1];
        float4 v0 = ((const float4*)(g_s + (long long)r0 * 128))[lane];
        float4 v1 = ((const float4*)(g_s + (long long)r1 * 128))[lane];
        acc.x += v0.x * a0 + v1.x * a1;
        acc.y += v0.y * a0 + v1.y * a1;
        acc.z += v0.z * a0 + v1.z * a1;
        acc.w += v0.w * a0 + v1.w * a1;
    }
    if (e < end) {
        int   r0 = g_csr_row[e];
        float a0 = g_csr_ea[e];
        float4 v0 = ((const float4*)(g_s + (long long)r0 * 128))[lane];
        acc.x += v0.x * a0; acc.y += v0.y * a0;
        acc.z += v0.z * a0; acc.w += v0.w * a0;
    }
    float iv = g_inv[n];
    acc.x *= iv; acc.y *= iv; acc.z *= iv; acc.w *= iv;
    ((float4*)(g_agg + (long long)n * 128))[lane] = acc;
}

// ---------------- SGEMM: double-buffered, FFMA2 (R11-proven core) -----------
// Output set selected per block: blockIdx.y < splitY -> (W, bias, Cid, Nc, act),
// else -> (W2, bias2, C2id, Nc2, act2) with yy = blockIdx.y - splitY.
// A = concat(A0[K0], A1[K1]) shared by both sets. BM=BN=128, BK=16, 256 thr.
__global__ __launch_bounds__(256)
void gemm_kernel(const float* __restrict__ A0p, int A0id, int K0,
                 int A1id, int K1,
                 const float* __restrict__ W,  const float* __restrict__ bias,
                 int Cid, int Nc, int act,
                 float* __restrict__ Cp, int M, int splitY,
                 const float* __restrict__ W2, const float* __restrict__ bias2,
                 int C2id, int Nc2, int act2) {
    const int BK = 16;
    __shared__ float As[2][BK][132];
    __shared__ float Bs[2][BK][132];

    const float* A0 = (A0id >= 0) ? buf(A0id) : A0p;
    const float* A1 = (A1id >= 0) ? buf(A1id) : nullptr;

    int yy = blockIdx.y;
    const float* Wp; const float* bp_; float* C; int NcS, actS;
    if ((int)blockIdx.y < splitY) {
        Wp = W;  bp_ = bias;  C = (Cid >= 0) ? buf(Cid) : Cp; NcS = Nc;  actS = act;
    } else {
        yy = blockIdx.y - splitY;
        Wp = W2; bp_ = bias2; C = buf(C2id);                  NcS = Nc2; actS = act2;
    }

    const int K  = K0 + K1;
    const int m0 = blockIdx.x * 128;
    const int n0 = yy * 128;
    const int t  = threadIdx.x;
    const int ty = t >> 4;          // 0..15
    const int tx = t & 15;          // 0..15

    // packed accumulators: acc[i][jp] holds (c[i][2jp], c[i][2jp+1])
    unsigned long long acc[8][4];
#pragma unroll
    for (int i = 0; i < 8; i++)
#pragma unroll
        for (int jp = 0; jp < 4; jp++) acc[i][jp] = 0ULL;

    float4 pa[2], pb[2];

    auto load_tiles = [&](int k0) {
#pragma unroll
        for (int q = 0; q < 2; q++) {
            int idx = t + q * 256;          // [0,512)
            int row = idx >> 2;             // 0..127
            int kc  = (idx & 3) * 4;        // 0,4,8,12
            int grow = m0 + row;
            float4 v = make_float4(0.f, 0.f, 0.f, 0.f);
            if (grow < M) {
                int kg = k0 + kc;
                if (kg < K0) v = *(const float4*)(A0 + (long long)grow * K0 + kg);
                else         v = *(const float4*)(A1 + (long long)grow * K1 + (kg - K0));
            }
            pa[q] = v;
            int kr = idx >> 5;              // 0..15
            int nc = (idx & 31) * 4;        // 0..124
            pb[q] = *(const float4*)(Wp + (long long)(k0 + kr) * NcS + n0 + nc);
        }
    };
    auto store_tiles = [&](int sbuf) {
#pragma unroll
        for (int q = 0; q < 2; q++) {
            int idx = t + q * 256;
            int row = idx >> 2;
            int kc  = (idx & 3) * 4;
            As[sbuf][kc + 0][row] = pa[q].x;
            As[sbuf][kc + 1][row] = pa[q].y;
            As[sbuf][kc + 2][row] = pa[q].z;
            As[sbuf][kc + 3][row] = pa[q].w;
            int kr = idx >> 5;
            int nc = (idx & 31) * 4;
            *(float4*)&Bs[sbuf][kr][nc] = pb[q];
        }
    };

    const int niter = K / BK;
    load_tiles(0);
    store_tiles(0);
    __syncthreads();
    int cur = 0;

    for (int it = 0; it < niter; it++) {
        if (it + 1 < niter) load_tiles((it + 1) * BK);

#pragma unroll
        for (int kk = 0; kk < BK; kk++) {
            float4 a0 = *(const float4*)&As[cur][kk][ty * 8];
            float4 a1 = *(const float4*)&As[cur][kk][ty * 8 + 4];
            // B pairs read directly as b64 (Bs rows are n-contiguous; same bits)
            ulonglong2 bq0 = *(const ulonglong2*)&Bs[cur][kk][tx * 8];
            ulonglong2 bq1 = *(const ulonglong2*)&Bs[cur][kk][tx * 8 + 4];
            unsigned long long b[4] = {bq0.x, bq0.y, bq1.x, bq1.y};
            float av[8] = {a0.x, a0.y, a0.z, a0.w, a1.x, a1.y, a1.z, a1.w};
#pragma unroll
            for (int i = 0; i < 8; i++) {
                unsigned long long aa;
                asm("mov.b64 %0, {%1,%1};" : "=l"(aa) : "f"(av[i]));
#pragma unroll
                for (int jp = 0; jp < 4; jp++) {
                    asm("fma.rn.f32x2 %0, %1, %2, %0;"
                        : "+l"(acc[i][jp]) : "l"(aa), "l"(b[jp]));
                }
            }
        }

        if (it + 1 < niter) {
            __syncthreads();
            store_tiles(cur ^ 1);
            cur ^= 1;
            __syncthreads();
        }
    }

    // --- epilogue: unpack + bias + activation + store (float4)
#pragma unroll
    for (int i = 0; i < 8; i++) {
        int grow = m0 + ty * 8 + i;
        if (grow >= M) continue;
        float c[8];
#pragma unroll
        for (int jp = 0; jp < 4; jp++) {
            asm("mov.b64 {%0,%1}, %2;"
                : "=f"(c[2 * jp]), "=f"(c[2 * jp + 1]) : "l"(acc[i][jp]));
        }
#pragma unroll
        for (int j = 0; j < 8; j += 4) {
            int gc = n0 + tx * 8 + j;
            float4 v;
            v.x = c[j + 0] + bp_[gc + 0];
            v.y = c[j + 1] + bp_[gc + 1];
            v.z = c[j + 2] + bp_[gc + 2];
            v.w = c[j + 3] + bp_[gc + 3];
            if (actS == 1) {
                v.x = v.x > 0.f ? v.x : 0.01f * v.x;
                v.y = v.y > 0.f ? v.y : 0.01f * v.y;
                v.z = v.z > 0.f ? v.z : 0.01f * v.z;
                v.w = v.w > 0.f ? v.w : 0.01f * v.w;
            }
            *(float4*)(C + (long long)grow * NcS + gc) = v;
        }
    }
}

// ---------------- GRU elementwise update (float4) ----------------------------
__global__ void gru_kernel(float* __restrict__ doutp, int writeOut) {
    int idx = blockIdx.x * blockDim.x + threadIdx.x;   // over NN*32
    if (idx >= NN * 32) return;
    int n  = idx >> 5;
    int j4 = idx & 31;
    const float4* gi4 = (const float4*)(g_gi + (long long)n * 384);
    const float4* gh4 = (const float4*)(g_gh + (long long)n * 384);
    float4 ir  = gi4[j4],      hr = gh4[j4];
    float4 iz  = gi4[32 + j4], hz = gh4[32 + j4];
    float4 inn = gi4[64 + j4], hn = gh4[64 + j4];
    float4 h   = ((const float4*)(g_h + (long long)n * 128))[j4];
    float4 o;
    {
        float r = 1.f / (1.f + __expf(-(ir.x + hr.x)));
        float z = 1.f / (1.f + __expf(-(iz.x + hz.x)));
        float nv = tanhf(inn.x + r * hn.x);
        o.x = (1.f - z) * nv + z * h.x;
    }
    {
        float r = 1.f / (1.f + __expf(-(ir.y + hr.y)));
        float z = 1.f / (1.f + __expf(-(iz.y + hz.y)));
        float nv = tanhf(inn.y + r * hn.y);
        o.y = (1.f - z) * nv + z * h.y;
    }
    {
        float r = 1.f / (1.f + __expf(-(ir.z + hr.z)));
        float z = 1.f / (1.f + __expf(-(iz.z + hz.z)));
        float nv = tanhf(inn.z + r * hn.z);
        o.z = (1.f - z) * nv + z * h.z;
    }
    {
        float r = 1.f / (1.f + __expf(-(ir.w + hr.w)));
        float z = 1.f / (1.f + __expf(-(iz.w + hz.w)));
        float nv = tanhf(inn.w + r * hn.w);
        o.w = (1.f - z) * nv + z * h.w;
    }
    if (writeOut) ((float4*)doutp)[idx] = o;
    else          ((float4*)g_h)[idx]  = o;
}

// ---------------- launch -----------------------------------------------------
extern "C" void kernel_launch(void* const* d_in, const int* in_sizes, int n_in,
                              void* d_out, int out_size) {
    const float* x  = (const float*)d_in[0];
    const int*   ei = (const int*)d_in[1];     // int32 (JAX x64 disabled)
    const float* ea = (const float*)d_in[2];
    // d_in[3] = batch (unused)
    const float* W_embed = (const float*)d_in[4];
    const float* b_embed = (const float*)d_in[5];
    const float* W_snd   = (const float*)d_in[6];
    const float* b_snd   = (const float*)d_in[7];
    const float* W_rec   = (const float*)d_in[8];
    const float* b_rec   = (const float*)d_in[9];
    const float* W_ih    = (const float*)d_in[10];
    const float* b_ih    = (const float*)d_in[11];
    const float* W_hh    = (const float*)d_in[12];
    const float* b_hh    = (const float*)d_in[13];

    const int T = 256;
    const int rowBlocks = (NN + 127) / 128;   // 391

    // CSR build (per call, deterministic work)
    zero_cnt_kernel<<<(NN + T - 1) / T, T>>>();
    count_kernel<<<(EE + T - 1) / T, T>>>(ei);
    scan_kernel<<<1, 1024>>>();
    fill_kernel<<<(EE + T - 1) / T, T>>>(ei, ea);

    // embed: h = x @ W_embed + b_embed
    gemm_kernel<<<dim3(rowBlocks, 1), T>>>(x, -1, 64, -1, 0,
                                           W_embed, b_embed, BUF_H, 128, 0,
                                           nullptr, NN, 99,
                                           nullptr, nullptr, BUF_H, 128, 0);

    for (int layer = 0; layer < 3; layer++) {
        // fused: s = leaky(h@W_snd+b) [y=0]  and  gh = h@W_hh+b [y=1..3]
        gemm_kernel<<<dim3(rowBlocks, 4), T>>>(nullptr, BUF_H, 128, -1, 0,
                                               W_snd, b_snd, BUF_S, 128, 1,
                                               nullptr, NN, 1,
                                               W_hh, b_hh, BUF_GH, 384, 0);
        // agg = segment_mean via CSR gather (no atomics)
        agg_kernel<<<(NN * 32 + T - 1) / T, T>>>();
        // m = leaky_relu([agg, h] @ W_rec + b_rec)
        gemm_kernel<<<dim3(rowBlocks, 2), T>>>(nullptr, BUF_AGG, 128, BUF_H, 128,
                                               W_rec, b_rec, BUF_M, 256, 1,
                                               nullptr, NN, 99,
                                               nullptr, nullptr, BUF_M, 256, 0);
        // gi = m @ W_ih + b_ih
        gemm_kernel<<<dim3(rowBlocks, 3), T>>>(nullptr, BUF_M, 256, -1, 0,
                                               W_ih, b_ih, BUF_GI, 384, 0,
                                               nullptr, NN, 99,
                                               nullptr, nullptr, BUF_GI, 384, 0);
        // GRU update (last layer writes d_out)
        gru_kernel<<<(NN * 32 + T - 1) / T, T>>>(
            (float*)d_out, layer == 2 ? 1 : 0);
    }
}

// round 15
// speedup vs baseline: 1.7644x; 1.4687x over previous
#include <cuda_runtime.h>
#include <cuda_bf16.h>
#include <cstdint>

// Problem constants
#define NN 50000
#define EE 800000

// ---------------- scratch (device globals; no allocation allowed) -----------
// fp32
__device__ float g_h  [(long long)NN * 128];
__device__ float g_s  [(long long)NN * 128];
__device__ float g_gi [(long long)NN * 384];
__device__ float g_gh [(long long)NN * 384];
__device__ float g_inv[NN];
__device__ int   g_cnt[NN];
__device__ int   g_start[NN + 1];
__device__ int   g_head[NN];
__device__ int   g_csr_row[EE];
__device__ float g_csr_ea[EE];
// bf16 split pairs (hi, lo) — 16B-aligned for uint4 access
__device__ __align__(16) __nv_bfloat16 g_xh [(long long)NN * 64];
__device__ __align__(16) __nv_bfloat16 g_xl [(long long)NN * 64];
__device__ __align__(16) __nv_bfloat16 g_hh [(long long)NN * 128];
__device__ __align__(16) __nv_bfloat16 g_hl [(long long)NN * 128];
__device__ __align__(16) __nv_bfloat16 g_agh[(long long)NN * 128];
__device__ __align__(16) __nv_bfloat16 g_agl[(long long)NN * 128];
__device__ __align__(16) __nv_bfloat16 g_mh [(long long)NN * 256];
__device__ __align__(16) __nv_bfloat16 g_ml [(long long)NN * 256];
// prepared weights: B' = [Bh; Bh; Bl], K-major [N][3K] bf16
__device__ __align__(16) __nv_bfloat16 g_wb[712704];

#define OFF_WE 0L
#define OFF_WS 24576L
#define OFF_WH 73728L
#define OFF_WR 221184L
#define OFF_WI 417792L

// f32 buffer ids
#define F_H  0
#define F_S  1
#define F_GI 2
#define F_GH 3
// bf16 buffer ids
#define B_XH 0
#define B_XL 1
#define B_HH 2
#define B_HL 3
#define B_AGH 4
#define B_AGL 5
#define B_MH 6
#define B_ML 7

__device__ __forceinline__ float* fbuf(int id) {
    switch (id) {
        case F_H:  return g_h;
        case F_S:  return g_s;
        case F_GI: return g_gi;
        case F_GH: return g_gh;
    }
    return nullptr;
}
__device__ __forceinline__ __nv_bfloat16* bbuf(int id) {
    switch (id) {
        case B_XH:  return g_xh;
        case B_XL:  return g_xl;
        case B_HH:  return g_hh;
        case B_HL:  return g_hl;
        case B_AGH: return g_agh;
        case B_AGL: return g_agl;
        case B_MH:  return g_mh;
        case B_ML:  return g_ml;
    }
    return nullptr;
}

__device__ __forceinline__ uint32_t smem_u32(const void* p) {
    uint32_t a;
    asm("{ .reg .u64 t; cvta.to.shared.u64 t, %1; cvt.u32.u64 %0, t; }"
        : "=r"(a) : "l"(p));
    return a;
}

// ---------------- prep kernels ------------------------------------------------
// Split+transpose weight W[K x N] fp32 -> B'[N][3K] bf16 = [Bh|Bh|Bl] along k'.
__global__ void wprep_kernel(const float* __restrict__ W, int K, int N, long off) {
    int idx = blockIdx.x * blockDim.x + threadIdx.x;
    if (idx >= K * N) return;
    int k = idx / N, n = idx % N;
    float w = W[idx];
    __nv_bfloat16 wh = __float2bfloat16(w);
    __nv_bfloat16 wl = __float2bfloat16(w - __bfloat162float(wh));
    long base = off + (long)n * 3 * K;
    g_wb[base + k]         = wh;
    g_wb[base + K + k]     = wh;
    g_wb[base + 2 * K + k] = wl;
}

__global__ void splitx_kernel(const float* __restrict__ x) {
    long i = (long)blockIdx.x * blockDim.x + threadIdx.x;
    if (i >= (long)NN * 64) return;
    float v = x[i];
    __nv_bfloat16 h = __float2bfloat16(v);
    g_xh[i] = h;
    g_xl[i] = __float2bfloat16(v - __bfloat162float(h));
}

// ---------------- degree / CSR build -----------------------------------------
__global__ void zero_cnt_kernel() {
    int i = blockIdx.x * blockDim.x + threadIdx.x;
    if (i < NN) g_cnt[i] = 0;
}
__global__ void count_kernel(const int* __restrict__ ei) {
    int e = blockIdx.x * blockDim.x + threadIdx.x;
    if (e < EE) {
        unsigned c = (unsigned)ei[EE + e];
        if (c < NN) atomicAdd(&g_cnt[c], 1);
    }
}
__global__ void scan_kernel() {
    __shared__ int ssum[1024];
    const int CH = (NN + 1023) / 1024;
    int t = threadIdx.x;
    int beg = t * CH;
    int end = beg + CH; if (end > NN) end = NN;
    int s = 0;
    for (int i = beg; i < end; i++) s += g_cnt[i];
    ssum[t] = s;
    __syncthreads();
    for (int off = 1; off < 1024; off <<= 1) {
        int v = (t >= off) ? ssum[t - off] : 0;
        __syncthreads();
        ssum[t] += v;
        __syncthreads();
    }
    int run = ssum[t] - s;
    for (int i = beg; i < end; i++) {
        int c = g_cnt[i];
        g_start[i] = run;
        g_head[i]  = run;
        g_inv[i]   = 1.0f / (float)(c > 0 ? c : 1);
        run += c;
    }
    if (t == 1023) g_start[NN] = ssum[1023];
}
__global__ void fill_kernel(const int* __restrict__ ei,
                            const float* __restrict__ ea) {
    int e = blockIdx.x * blockDim.x + threadIdx.x;
    if (e >= EE) return;
    unsigned r = (unsigned)ei[e];
    unsigned c = (unsigned)ei[EE + e];
    if (c < NN) {
        int p = atomicAdd(&g_head[c], 1);
        g_csr_row[p] = (r < NN) ? (int)r : 0;
        g_csr_ea[p]  = ea[e];
    }
}

// ---------------- aggregation: CSR gather, outputs bf16 split pair -----------
__global__ void agg_kernel() {
    int gid  = blockIdx.x * blockDim.x + threadIdx.x;
    int n    = gid >> 5;
    int lane = gid & 31;
    if (n >= NN) return;
    int beg = g_start[n];
    int end = g_start[n + 1];
    float4 acc = make_float4(0.f, 0.f, 0.f, 0.f);
    int e = beg;
    for (; e + 1 < end; e += 2) {
        int   r0 = g_csr_row[e];
        int   r1 = g_csr_row[e + 1];
        float a0 = g_csr_ea[e];
        float a1 = g_csr_ea[e + 1];
        float4 v0 = ((const float4*)(g_s + (long long)r0 * 128))[lane];
        float4 v1 = ((const float4*)(g_s + (long long)r1 * 128))[lane];
        acc.x += v0.x * a0 + v1.x * a1;
        acc.y += v0.y * a0 + v1.y * a1;
        acc.z += v0.z * a0 + v1.z * a1;
        acc.w += v0.w * a0 + v1.w * a1;
    }
    if (e < end) {
        int   r0 = g_csr_row[e];
        float a0 = g_csr_ea[e];
        float4 v0 = ((const float4*)(g_s + (long long)r0 * 128))[lane];
        acc.x += v0.x * a0; acc.y += v0.y * a0;
        acc.z += v0.z * a0; acc.w += v0.w * a0;
    }
    float iv = g_inv[n];
    float vals[4] = {acc.x * iv, acc.y * iv, acc.z * iv, acc.w * iv};
    long base = (long)n * 128 + lane * 4;
#pragma unroll
    for (int k = 0; k < 4; k++) {
        __nv_bfloat16 h = __float2bfloat16(vals[k]);
        g_agh[base + k] = h;
        g_agl[base + k] = __float2bfloat16(vals[k] - __bfloat162float(h));
    }
}

// ---------------- bf16-split warp-MMA GEMM (mma.sync m16n8k16) ---------------
// C[M x Nc] = act( concat(A0, A1)[M x (K0+K1)] @ W[(K0+K1) x Nc] + bias )
// A as bf16 split pairs, W pre-split in g_wb as [Nc][3K'] K-major bf16.
// CTA 256 thr = 8 warps (4m x 2n), tile 128x128; K' chunks of 32, dbuf smem.
#define SPITCH 40   // smem row stride in bf16 (conflict-free for ldmatrix)

__global__ __launch_bounds__(256)
void mma_gemm(int a0h, int a0l, int K0, int a1h, int a1l, int K1,
              long wOff, const float* __restrict__ bias,
              int outF32, int outH, int outL,
              int M, int Nc, int act) {
    __shared__ __align__(16) __nv_bfloat16 sA[2][128][SPITCH];
    __shared__ __align__(16) __nv_bfloat16 sB[2][128][SPITCH];

    const int t    = threadIdx.x;
    const int lane = t & 31;
    const int wid  = t >> 5;
    const int warpM = wid >> 1;          // 0..3
    const int warpN = wid & 1;           // 0..1
    const int m0 = blockIdx.x * 128;
    const int n0 = blockIdx.y * 128;

    const __nv_bfloat16* A0h = bbuf(a0h);
    const __nv_bfloat16* A0l = bbuf(a0l);
    const __nv_bfloat16* A1h = (a1h >= 0) ? bbuf(a1h) : nullptr;
    const __nv_bfloat16* A1l = (a1l >= 0) ? bbuf(a1l) : nullptr;
    const __nv_bfloat16* Bw  = g_wb + wOff;

    const int Ksum  = K0 + K1;
    const int Kp    = 3 * Ksum;
    const int niter = Kp / 32;

    float acc[2][8][4];
#pragma unroll
    for (int i = 0; i < 2; i++)
#pragma unroll
        for (int j = 0; j < 8; j++)
#pragma unroll
            for (int k = 0; k < 4; k++) acc[i][j][k] = 0.f;

    uint4 pa[2], pb[2];
    const uint4 zz = make_uint4(0, 0, 0, 0);

    auto load_chunk = [&](int kp) {
        int seg = kp / Ksum;
        int kg  = kp - seg * Ksum;
        const __nv_bfloat16* As;
        int pitch;
        if (kg < K0) { As = (seg == 1) ? A0l : A0h; pitch = K0; }
        else         { As = (seg == 1) ? A1l : A1h; pitch = K1; kg -= K0; }
#pragma unroll
        for (int q = 0; q < 2; q++) {
            int idx  = t + q * 256;       // [0,512)
            int row  = idx >> 2;          // 0..127
            int part = idx & 3;           // 16B piece
            int grow = m0 + row;
            pa[q] = (grow < M)
                ? *(const uint4*)(As + (long)grow * pitch + kg + part * 8) : zz;
            pb[q] = *(const uint4*)(Bw + (long)(n0 + row) * Kp + kp + part * 8);
        }
    };
    auto store_chunk = [&](int buf) {
#pragma unroll
        for (int q = 0; q < 2; q++) {
            int idx  = t + q * 256;
            int row  = idx >> 2;
            int part = idx & 3;
            *(uint4*)&sA[buf][row][part * 8] = pa[q];
            *(uint4*)&sB[buf][row][part * 8] = pb[q];
        }
    };

    load_chunk(0);
    store_chunk(0);
    __syncthreads();
    int cur = 0;

    for (int it = 0; it < niter; it++) {
        if (it + 1 < niter) load_chunk((it + 1) * 32);

        uint32_t baseA = smem_u32(&sA[cur][0][0]);
        uint32_t baseB = smem_u32(&sB[cur][0][0]);
#pragma unroll
        for (int ks = 0; ks < 2; ks++) {
            // A fragments: 2 x (m16 x k16) via ldmatrix.x4 (no trans)
            uint32_t af[2][4];
#pragma unroll
            for (int mf = 0; mf < 2; mf++) {
                int r = warpM * 32 + mf * 16 + (lane & 15);
                int c = ks * 16 + ((lane >> 4) & 1) * 8;
                uint32_t ad = baseA + (uint32_t)(r * SPITCH + c) * 2;
                asm volatile(
                    "ldmatrix.sync.aligned.m8n8.x4.shared.b16 {%0,%1,%2,%3}, [%4];"
                    : "=r"(af[mf][0]), "=r"(af[mf][1]),
                      "=r"(af[mf][2]), "=r"(af[mf][3]) : "r"(ad));
            }
            // B fragments: 8 nfrags as 4 pairs via ldmatrix.x4 on B'[n][k] rows
            uint32_t bf[8][2];
#pragma unroll
            for (int np = 0; np < 4; np++) {
                int n = warpN * 64 + np * 16 + ((lane >> 4) & 1) * 8 + (lane & 7);
                int c = ks * 16 + ((lane >> 3) & 1) * 8;
                uint32_t bd = baseB + (uint32_t)(n * SPITCH + c) * 2;
                asm volatile(
                    "ldmatrix.sync.aligned.m8n8.x4.shared.b16 {%0,%1,%2,%3}, [%4];"
                    : "=r"(bf[2 * np][0]), "=r"(bf[2 * np][1]),
                      "=r"(bf[2 * np + 1][0]), "=r"(bf[2 * np + 1][1]) : "r"(bd));
            }
#pragma unroll
            for (int mf = 0; mf < 2; mf++)
#pragma unroll
                for (int nf = 0; nf < 8; nf++) {
                    asm volatile(
                        "mma.sync.aligned.m16n8k16.row.col.f32.bf16.bf16.f32 "
                        "{%0,%1,%2,%3}, {%4,%5,%6,%7}, {%8,%9}, {%0,%1,%2,%3};"
                        : "+f"(acc[mf][nf][0]), "+f"(acc[mf][nf][1]),
                          "+f"(acc[mf][nf][2]), "+f"(acc[mf][nf][3])
                        : "r"(af[mf][0]), "r"(af[mf][1]),
                          "r"(af[mf][2]), "r"(af[mf][3]),
                          "r"(bf[nf][0]), "r"(bf[nf][1]));
                }
        }

        if (it + 1 < niter) {
            __syncthreads();
            store_chunk(cur ^ 1);
            cur ^= 1;
            __syncthreads();
        }
    }

    // --- epilogue: bias + act + fp32 and/or bf16-split stores
    float* Cf = (outF32 >= 0) ? fbuf(outF32) : nullptr;
    __nv_bfloat16* Ch = (outH >= 0) ? bbuf(outH) : nullptr;
    __nv_bfloat16* Cl = (outH >= 0) ? bbuf(outL) : nullptr;

#pragma unroll
    for (int mf = 0; mf < 2; mf++) {
#pragma unroll
        for (int nf = 0; nf < 8; nf++) {
            int col = n0 + warpN * 64 + nf * 8 + 2 * (lane & 3);
            float bb0 = bias[col], bb1 = bias[col + 1];
#pragma unroll
            for (int half = 0; half < 2; half++) {
                int row = m0 + warpM * 32 + mf * 16 + (lane >> 2) + half * 8;
                if (row >= M) continue;
                float v0 = acc[mf][nf][2 * half + 0] + bb0;
                float v1 = acc[mf][nf][2 * half + 1] + bb1;
                if (act == 1) {
                    v0 = v0 > 0.f ? v0 : 0.01f * v0;
                    v1 = v1 > 0.f ? v1 : 0.01f * v1;
                }
                long o = (long)row * Nc + col;
                if (Cf) *(float2*)(Cf + o) = make_float2(v0, v1);
                if (Ch) {
                    __nv_bfloat16 h0 = __float2bfloat16(v0);
                    __nv_bfloat16 h1 = __float2bfloat16(v1);
                    __nv_bfloat162 hv; hv.x = h0; hv.y = h1;
                    *(__nv_bfloat162*)(Ch + o) = hv;
                    __nv_bfloat162 lv;
                    lv.x = __float2bfloat16(v0 - __bfloat162float(h0));
                    lv.y = __float2bfloat16(v1 - __bfloat162float(h1));
                    *(__nv_bfloat162*)(Cl + o) = lv;
                }
            }
        }
    }
}

// ---------------- GRU elementwise update + bf16 split out --------------------
__global__ void gru_kernel(float* __restrict__ doutp, int writeOut) {
    int idx = blockIdx.x * blockDim.x + threadIdx.x;   // over NN*32
    if (idx >= NN * 32) return;
    int n  = idx >> 5;
    int j4 = idx & 31;
    const float4* gi4 = (const float4*)(g_gi + (long long)n * 384);
    const float4* gh4 = (const float4*)(g_gh + (long long)n * 384);
    float4 ir  = gi4[j4],      hr = gh4[j4];
    float4 iz  = gi4[32 + j4], hz = gh4[32 + j4];
    float4 inn = gi4[64 + j4], hn = gh4[64 + j4];
    float4 h   = ((const float4*)(g_h + (long long)n * 128))[j4];
    float o[4];
    float irv[4] = {ir.x, ir.y, ir.z, ir.w};
    float hrv[4] = {hr.x, hr.y, hr.z, hr.w};
    float izv[4] = {iz.x, iz.y, iz.z, iz.w};
    float hzv[4] = {hz.x, hz.y, hz.z, hz.w};
    float inv_[4] = {inn.x, inn.y, inn.z, inn.w};
    float hnv[4] = {hn.x, hn.y, hn.z, hn.w};
    float hv[4]  = {h.x, h.y, h.z, h.w};
#pragma unroll
    for (int k = 0; k < 4; k++) {
        float r = 1.f / (1.f + __expf(-(irv[k] + hrv[k])));
        float z = 1.f / (1.f + __expf(-(izv[k] + hzv[k])));
        float nv = tanhf(inv_[k] + r * hnv[k]);
        o[k] = (1.f - z) * nv + z * hv[k];
    }
    float4 o4 = make_float4(o[0], o[1], o[2], o[3]);
    if (writeOut) ((float4*)doutp)[idx] = o4;
    ((float4*)g_h)[idx] = o4;
    long base = (long)n * 128 + j4 * 4;
#pragma unroll
    for (int k = 0; k < 4; k++) {
        __nv_bfloat16 hh = __float2bfloat16(o[k]);
        g_hh[base + k] = hh;
        g_hl[base + k] = __float2bfloat16(o[k] - __bfloat162float(hh));
    }
}

// ---------------- launch -----------------------------------------------------
extern "C" void kernel_launch(void* const* d_in, const int* in_sizes, int n_in,
                              void* d_out, int out_size) {
    const float* x  = (const float*)d_in[0];
    const int*   ei = (const int*)d_in[1];     // int32 (JAX x64 disabled)
    const float* ea = (const float*)d_in[2];
    // d_in[3] = batch (unused)
    const float* W_embed = (const float*)d_in[4];
    const float* b_embed = (const float*)d_in[5];
    const float* W_snd   = (const float*)d_in[6];
    const float* b_snd   = (const float*)d_in[7];
    const float* W_rec   = (const float*)d_in[8];
    const float* b_rec   = (const float*)d_in[9];
    const float* W_ih    = (const float*)d_in[10];
    const float* b_ih    = (const float*)d_in[11];
    const float* W_hh    = (const float*)d_in[12];
    const float* b_hh    = (const float*)d_in[13];

    const int T = 256;
    const int rowBlocks = (NN + 127) / 128;   // 391

    // weight prep (split + transpose to K-major bf16 [Bh|Bh|Bl])
    wprep_kernel<<<(64 * 128 + T - 1) / T, T>>>(W_embed, 64, 128, OFF_WE);
    wprep_kernel<<<(128 * 128 + T - 1) / T, T>>>(W_snd, 128, 128, OFF_WS);
    wprep_kernel<<<(128 * 384 + T - 1) / T, T>>>(W_hh, 128, 384, OFF_WH);
    wprep_kernel<<<(256 * 256 + T - 1) / T, T>>>(W_rec, 256, 256, OFF_WR);
    wprep_kernel<<<(256 * 384 + T - 1) / T, T>>>(W_ih, 256, 384, OFF_WI);
    splitx_kernel<<<(NN * 64 + T - 1) / T, T>>>(x);

    // CSR build
    zero_cnt_kernel<<<(NN + T - 1) / T, T>>>();
    count_kernel<<<(EE + T - 1) / T, T>>>(ei);
    scan_kernel<<<1, 1024>>>();
    fill_kernel<<<(EE + T - 1) / T, T>>>(ei, ea);

    // embed: h = x @ W_embed + b_embed  (writes h fp32 + (hh,hl) pair)
    mma_gemm<<<dim3(rowBlocks, 1), T>>>(B_XH, B_XL, 64, -1, -1, 0,
                                        OFF_WE, b_embed,
                                        F_H, B_HH, B_HL, NN, 128, 0);

    for (int layer = 0; layer < 3; layer++) {
        // s = leaky(h @ W_snd + b)
        mma_gemm<<<dim3(rowBlocks, 1), T>>>(B_HH, B_HL, 128, -1, -1, 0,
                                            OFF_WS, b_snd,
                                            F_S, -1, -1, NN, 128, 1);
        // gh = h @ W_hh + b
        mma_gemm<<<dim3(rowBlocks, 3), T>>>(B_HH, B_HL, 128, -1, -1, 0,
                                            OFF_WH, b_hh,
                                            F_GH, -1, -1, NN, 384, 0);
        // agg = segment_mean via CSR gather -> (aggh, aggl)
        agg_kernel<<<(NN * 32 + T - 1) / T, T>>>();
        // m = leaky([agg, h] @ W_rec + b) -> (mh, ml)
        mma_gemm<<<dim3(rowBlocks, 2), T>>>(B_AGH, B_AGL, 128, B_HH, B_HL, 128,
                                            OFF_WR, b_rec,
                                            -1, B_MH, B_ML, NN, 256, 1);
        // gi = m @ W_ih + b
        mma_gemm<<<dim3(rowBlocks, 3), T>>>(B_MH, B_ML, 256, -1, -1, 0,
                                            OFF_WI, b_ih,
                                            F_GI, -1, -1, NN, 384, 0);
        // GRU update: writes h fp32 + (hh,hl); last layer also d_out
        gru_kernel<<<(NN * 32 + T - 1) / T, T>>>(
            (float*)d_out, layer == 2 ? 1 : 0);
    }
}

// round 16
// speedup vs baseline: 2.1831x; 1.2373x over previous
#include <cuda_runtime.h>
#include <cuda_bf16.h>
#include <cstdint>

// Problem constants
#define NN 50000
#define EE 800000

// ---------------- scratch (device globals; no allocation allowed) -----------
// fp32
__device__ float g_h  [(long long)NN * 128];
__device__ float g_s  [(long long)NN * 128];
__device__ float g_gi [(long long)NN * 384];
__device__ float g_gh [(long long)NN * 384];
__device__ float g_inv[NN];
__device__ int   g_cnt[NN];
__device__ int   g_start[NN + 1];
__device__ int   g_head[NN];
__device__ int   g_csr_row[EE];
__device__ float g_csr_ea[EE];
// bf16 split pairs (hi, lo) — 16B-aligned for uint4 access
__device__ __align__(16) __nv_bfloat16 g_xh [(long long)NN * 64];
__device__ __align__(16) __nv_bfloat16 g_xl [(long long)NN * 64];
__device__ __align__(16) __nv_bfloat16 g_hh [(long long)NN * 128];
__device__ __align__(16) __nv_bfloat16 g_hl [(long long)NN * 128];
__device__ __align__(16) __nv_bfloat16 g_agh[(long long)NN * 128];
__device__ __align__(16) __nv_bfloat16 g_agl[(long long)NN * 128];
__device__ __align__(16) __nv_bfloat16 g_mh [(long long)NN * 256];
__device__ __align__(16) __nv_bfloat16 g_ml [(long long)NN * 256];
// prepared weights: B' = [Bh; Bh; Bl], K-major [N][3K] bf16
__device__ __align__(16) __nv_bfloat16 g_wb[712704];

#define OFF_WE 0L
#define OFF_WS 24576L
#define OFF_WH 73728L
#define OFF_WR 221184L
#define OFF_WI 417792L

// f32 buffer ids
#define F_H  0
#define F_S  1
#define F_GI 2
#define F_GH 3
// bf16 buffer ids
#define B_XH 0
#define B_XL 1
#define B_HH 2
#define B_HL 3
#define B_AGH 4
#define B_AGL 5
#define B_MH 6
#define B_ML 7

__device__ __forceinline__ float* fbuf(int id) {
    switch (id) {
        case F_H:  return g_h;
        case F_S:  return g_s;
        case F_GI: return g_gi;
        case F_GH: return g_gh;
    }
    return nullptr;
}
__device__ __forceinline__ __nv_bfloat16* bbuf(int id) {
    switch (id) {
        case B_XH:  return g_xh;
        case B_XL:  return g_xl;
        case B_HH:  return g_hh;
        case B_HL:  return g_hl;
        case B_AGH: return g_agh;
        case B_AGL: return g_agl;
        case B_MH:  return g_mh;
        case B_ML:  return g_ml;
    }
    return nullptr;
}

__device__ __forceinline__ uint32_t smem_u32(const void* p) {
    uint32_t a;
    asm("{ .reg .u64 t; cvta.to.shared.u64 t, %1; cvt.u32.u64 %0, t; }"
        : "=r"(a) : "l"(p));
    return a;
}
__device__ __forceinline__ void cp16(uint32_t dst, const void* src) {
    asm volatile("cp.async.cg.shared.global [%0], [%1], 16;"
        :: "r"(dst), "l"(src));
}
#define CP_COMMIT() asm volatile("cp.async.commit_group;" ::: "memory")
#define CP_WAIT1()  asm volatile("cp.async.wait_group 1;" ::: "memory")

// ---------------- prep kernels ------------------------------------------------
// Split+transpose weight W[K x N] fp32 -> B'[N][3K] bf16 = [Bh|Bh|Bl] along k'.
__global__ void wprep_kernel(const float* __restrict__ W, int K, int N, long off) {
    int idx = blockIdx.x * blockDim.x + threadIdx.x;
    if (idx >= K * N) return;
    int k = idx / N, n = idx % N;
    float w = W[idx];
    __nv_bfloat16 wh = __float2bfloat16(w);
    __nv_bfloat16 wl = __float2bfloat16(w - __bfloat162float(wh));
    long base = off + (long)n * 3 * K;
    g_wb[base + k]         = wh;
    g_wb[base + K + k]     = wh;
    g_wb[base + 2 * K + k] = wl;
}

__global__ void splitx_kernel(const float* __restrict__ x) {
    long i = (long)blockIdx.x * blockDim.x + threadIdx.x;
    if (i >= (long)NN * 64) return;
    float v = x[i];
    __nv_bfloat16 h = __float2bfloat16(v);
    g_xh[i] = h;
    g_xl[i] = __float2bfloat16(v - __bfloat162float(h));
}

// ---------------- degree / CSR build -----------------------------------------
__global__ void zero_cnt_kernel() {
    int i = blockIdx.x * blockDim.x + threadIdx.x;
    if (i < NN) g_cnt[i] = 0;
}
__global__ void count_kernel(const int* __restrict__ ei) {
    int e = blockIdx.x * blockDim.x + threadIdx.x;
    if (e < EE) {
        unsigned c = (unsigned)ei[EE + e];
        if (c < NN) atomicAdd(&g_cnt[c], 1);
    }
}
__global__ void scan_kernel() {
    __shared__ int ssum[1024];
    const int CH = (NN + 1023) / 1024;
    int t = threadIdx.x;
    int beg = t * CH;
    int end = beg + CH; if (end > NN) end = NN;
    int s = 0;
    for (int i = beg; i < end; i++) s += g_cnt[i];
    ssum[t] = s;
    __syncthreads();
    for (int off = 1; off < 1024; off <<= 1) {
        int v = (t >= off) ? ssum[t - off] : 0;
        __syncthreads();
        ssum[t] += v;
        __syncthreads();
    }
    int run = ssum[t] - s;
    for (int i = beg; i < end; i++) {
        int c = g_cnt[i];
        g_start[i] = run;
        g_head[i]  = run;
        g_inv[i]   = 1.0f / (float)(c > 0 ? c : 1);
        run += c;
    }
    if (t == 1023) g_start[NN] = ssum[1023];
}
__global__ void fill_kernel(const int* __restrict__ ei,
                            const float* __restrict__ ea) {
    int e = blockIdx.x * blockDim.x + threadIdx.x;
    if (e >= EE) return;
    unsigned r = (unsigned)ei[e];
    unsigned c = (unsigned)ei[EE + e];
    if (c < NN) {
        int p = atomicAdd(&g_head[c], 1);
        g_csr_row[p] = (r < NN) ? (int)r : 0;
        g_csr_ea[p]  = ea[e];
    }
}

// ---------------- aggregation: CSR gather (MLP=4), bf16 split out ------------
__global__ void agg_kernel() {
    int gid  = blockIdx.x * blockDim.x + threadIdx.x;
    int n    = gid >> 5;
    int lane = gid & 31;
    if (n >= NN) return;
    int beg = g_start[n];
    int end = g_start[n + 1];
    float4 acc = make_float4(0.f, 0.f, 0.f, 0.f);
    int e = beg;
    for (; e + 3 < end; e += 4) {
        int r0 = g_csr_row[e],     r1 = g_csr_row[e + 1];
        int r2 = g_csr_row[e + 2], r3 = g_csr_row[e + 3];
        float a0 = g_csr_ea[e],     a1 = g_csr_ea[e + 1];
        float a2 = g_csr_ea[e + 2], a3 = g_csr_ea[e + 3];
        float4 v0 = ((const float4*)(g_s + (long long)r0 * 128))[lane];
        float4 v1 = ((const float4*)(g_s + (long long)r1 * 128))[lane];
        float4 v2 = ((const float4*)(g_s + (long long)r2 * 128))[lane];
        float4 v3 = ((const float4*)(g_s + (long long)r3 * 128))[lane];
        acc.x += v0.x * a0 + v1.x * a1 + v2.x * a2 + v3.x * a3;
        acc.y += v0.y * a0 + v1.y * a1 + v2.y * a2 + v3.y * a3;
        acc.z += v0.z * a0 + v1.z * a1 + v2.z * a2 + v3.z * a3;
        acc.w += v0.w * a0 + v1.w * a1 + v2.w * a2 + v3.w * a3;
    }
    for (; e < end; e++) {
        int   r0 = g_csr_row[e];
        float a0 = g_csr_ea[e];
        float4 v0 = ((const float4*)(g_s + (long long)r0 * 128))[lane];
        acc.x += v0.x * a0; acc.y += v0.y * a0;
        acc.z += v0.z * a0; acc.w += v0.w * a0;
    }
    float iv = g_inv[n];
    float vals[4] = {acc.x * iv, acc.y * iv, acc.z * iv, acc.w * iv};
    long base = (long)n * 128 + lane * 4;
#pragma unroll
    for (int k = 0; k < 4; k++) {
        __nv_bfloat16 h = __float2bfloat16(vals[k]);
        g_agh[base + k] = h;
        g_agl[base + k] = __float2bfloat16(vals[k] - __bfloat162float(h));
    }
}

// ---------------- bf16-split warp-MMA GEMM, cp.async 3-stage pipeline --------
// C[M x Nc] = act( concat(A0, A1)[M x (K0+K1)] @ W[(K0+K1) x Nc] + bias )
// A as bf16 split pairs, W pre-split in g_wb as [Nc][3K'] K-major bf16.
// CTA 256 thr = 8 warps (4m x 2n), tile 128x128; K' chunks of 32.
// Smem per stage: A 128x64B + B 128x64B = 16KB; 3 stages = 48KB (exact limit).
// 16B-slot XOR swizzle: part' = part ^ ((row>>1)&3) — conflict-free stores +
// ldmatrix (even rows permute slots 0-3, odd rows slots 4-7).
#define NSTAGE 3

__global__ __launch_bounds__(256)
void mma_gemm(int a0h, int a0l, int K0, int a1h, int a1l, int K1,
              long wOff, const float* __restrict__ bias,
              int outF32, int outH, int outL,
              int M, int Nc, int act) {
    __shared__ __align__(16) unsigned char sm[NSTAGE][16384];  // [A 8K | B 8K]

    const int t    = threadIdx.x;
    const int lane = t & 31;
    const int wid  = t >> 5;
    const int warpM = wid >> 1;          // 0..3
    const int warpN = wid & 1;           // 0..1
    const int m0 = blockIdx.x * 128;
    const int n0 = blockIdx.y * 128;

    const __nv_bfloat16* A0h = bbuf(a0h);
    const __nv_bfloat16* A0l = bbuf(a0l);
    const __nv_bfloat16* A1h = (a1h >= 0) ? bbuf(a1h) : nullptr;
    const __nv_bfloat16* A1l = (a1l >= 0) ? bbuf(a1l) : nullptr;
    const __nv_bfloat16* Bw  = g_wb + wOff;

    const int Ksum  = K0 + K1;
    const int Kp    = 3 * Ksum;
    const int niter = Kp / 32;

    const uint32_t sbase = smem_u32(sm);

    float acc[2][8][4];
#pragma unroll
    for (int i = 0; i < 2; i++)
#pragma unroll
        for (int j = 0; j < 8; j++)
#pragma unroll
            for (int k = 0; k < 4; k++) acc[i][j][k] = 0.f;

    auto issue = [&](int ch) {
        int kp  = ch * 32;
        int seg = kp / Ksum;
        int kg  = kp - seg * Ksum;
        const __nv_bfloat16* As;
        int pitch;
        if (kg < K0) { As = (seg == 1) ? A0l : A0h; pitch = K0; }
        else         { As = (seg == 1) ? A1l : A1h; pitch = K1; kg -= K0; }
        uint32_t stA = sbase + (ch % NSTAGE) * 16384;
        uint32_t stB = stA + 8192;
#pragma unroll
        for (int q = 0; q < 2; q++) {
            int idx  = t + q * 256;       // [0,512)
            int row  = idx >> 2;          // 0..127
            int part = idx & 3;           // 16B slot within 64B row
            uint32_t sw = (uint32_t)((part ^ ((row >> 1) & 3)) * 16);
            int grow = m0 + row; if (grow >= M) grow = M - 1;   // clamp (discarded)
            cp16(stA + row * 64 + sw,
                 As + (long)grow * pitch + kg + part * 8);
            cp16(stB + row * 64 + sw,
                 Bw + (long)(n0 + row) * Kp + kp + part * 8);
        }
    };

    auto compute = [&](int slot) {
        uint32_t stA = sbase + slot * 16384;
        uint32_t stB = stA + 8192;
#pragma unroll
        for (int ks = 0; ks < 2; ks++) {
            uint32_t af[2][4];
#pragma unroll
            for (int mf = 0; mf < 2; mf++) {
                int r = warpM * 32 + mf * 16 + (lane & 15);
                int cpart = ks * 2 + ((lane >> 4) & 1);
                uint32_t ad = stA + (uint32_t)(r * 64 +
                              ((cpart ^ ((r >> 1) & 3)) * 16));
                asm volatile(
                    "ldmatrix.sync.aligned.m8n8.x4.shared.b16 {%0,%1,%2,%3}, [%4];"
                    : "=r"(af[mf][0]), "=r"(af[mf][1]),
                      "=r"(af[mf][2]), "=r"(af[mf][3]) : "r"(ad));
            }
            uint32_t bf[8][2];
#pragma unroll
            for (int np = 0; np < 4; np++) {
                int n = warpN * 64 + np * 16 + ((lane >> 4) & 1) * 8 + (lane & 7);
                int cpart = ks * 2 + ((lane >> 3) & 1);
                uint32_t bd = stB + (uint32_t)(n * 64 +
                              ((cpart ^ ((n >> 1) & 3)) * 16));
                asm volatile(
                    "ldmatrix.sync.aligned.m8n8.x4.shared.b16 {%0,%1,%2,%3}, [%4];"
                    : "=r"(bf[2 * np][0]), "=r"(bf[2 * np][1]),
                      "=r"(bf[2 * np + 1][0]), "=r"(bf[2 * np + 1][1]) : "r"(bd));
            }
#pragma unroll
            for (int mf = 0; mf < 2; mf++)
#pragma unroll
                for (int nf = 0; nf < 8; nf++) {
                    asm volatile(
                        "mma.sync.aligned.m16n8k16.row.col.f32.bf16.bf16.f32 "
                        "{%0,%1,%2,%3}, {%4,%5,%6,%7}, {%8,%9}, {%0,%1,%2,%3};"
                        : "+f"(acc[mf][nf][0]), "+f"(acc[mf][nf][1]),
                          "+f"(acc[mf][nf][2]), "+f"(acc[mf][nf][3])
                        : "r"(af[mf][0]), "r"(af[mf][1]),
                          "r"(af[mf][2]), "r"(af[mf][3]),
                          "r"(bf[nf][0]), "r"(bf[nf][1]));
                }
        }
    };

    // prologue: stages 0..NSTAGE-2
#pragma unroll
    for (int st = 0; st < NSTAGE - 1; st++) {
        if (st < niter) issue(st);
        CP_COMMIT();
    }
    for (int it = 0; it < niter; it++) {
        CP_WAIT1();          // group 'it' complete (in-order; empty commits pad)
        __syncthreads();     // all warps see stage, done computing stage it-1
        int nst = it + NSTAGE - 1;
        if (nst < niter) issue(nst);
        CP_COMMIT();
        compute(it % NSTAGE);
    }

    // --- epilogue: bias + act + fp32 and/or bf16-split stores
    float* Cf = (outF32 >= 0) ? fbuf(outF32) : nullptr;
    __nv_bfloat16* Ch = (outH >= 0) ? bbuf(outH) : nullptr;
    __nv_bfloat16* Cl = (outH >= 0) ? bbuf(outL) : nullptr;

#pragma unroll
    for (int mf = 0; mf < 2; mf++) {
#pragma unroll
        for (int nf = 0; nf < 8; nf++) {
            int col = n0 + warpN * 64 + nf * 8 + 2 * (lane & 3);
            float bb0 = bias[col], bb1 = bias[col + 1];
#pragma unroll
            for (int half = 0; half < 2; half++) {
                int row = m0 + warpM * 32 + mf * 16 + (lane >> 2) + half * 8;
                if (row >= M) continue;
                float v0 = acc[mf][nf][2 * half + 0] + bb0;
                float v1 = acc[mf][nf][2 * half + 1] + bb1;
                if (act == 1) {
                    v0 = v0 > 0.f ? v0 : 0.01f * v0;
                    v1 = v1 > 0.f ? v1 : 0.01f * v1;
                }
                long o = (long)row * Nc + col;
                if (Cf) *(float2*)(Cf + o) = make_float2(v0, v1);
                if (Ch) {
                    __nv_bfloat16 h0 = __float2bfloat16(v0);
                    __nv_bfloat16 h1 = __float2bfloat16(v1);
                    __nv_bfloat162 hv; hv.x = h0; hv.y = h1;
                    *(__nv_bfloat162*)(Ch + o) = hv;
                    __nv_bfloat162 lv;
                    lv.x = __float2bfloat16(v0 - __bfloat162float(h0));
                    lv.y = __float2bfloat16(v1 - __bfloat162float(h1));
                    *(__nv_bfloat162*)(Cl + o) = lv;
                }
            }
        }
    }
}

// ---------------- GRU elementwise update + bf16 split out --------------------
__global__ void gru_kernel(float* __restrict__ doutp, int writeOut) {
    int idx = blockIdx.x * blockDim.x + threadIdx.x;   // over NN*32
    if (idx >= NN * 32) return;
    int n  = idx >> 5;
    int j4 = idx & 31;
    const float4* gi4 = (const float4*)(g_gi + (long long)n * 384);
    const float4* gh4 = (const float4*)(g_gh + (long long)n * 384);
    float4 ir  = gi4[j4],      hr = gh4[j4];
    float4 iz  = gi4[32 + j4], hz = gh4[32 + j4];
    float4 inn = gi4[64 + j4], hn = gh4[64 + j4];
    float4 h   = ((const float4*)(g_h + (long long)n * 128))[j4];
    float o[4];
    float irv[4] = {ir.x, ir.y, ir.z, ir.w};
    float hrv[4] = {hr.x, hr.y, hr.z, hr.w};
    float izv[4] = {iz.x, iz.y, iz.z, iz.w};
    float hzv[4] = {hz.x, hz.y, hz.z, hz.w};
    float inv_[4] = {inn.x, inn.y, inn.z, inn.w};
    float hnv[4] = {hn.x, hn.y, hn.z, hn.w};
    float hv[4]  = {h.x, h.y, h.z, h.w};
#pragma unroll
    for (int k = 0; k < 4; k++) {
        float r = 1.f / (1.f + __expf(-(irv[k] + hrv[k])));
        float z = 1.f / (1.f + __expf(-(izv[k] + hzv[k])));
        float nv = tanhf(inv_[k] + r * hnv[k]);
        o[k] = (1.f - z) * nv + z * hv[k];
    }
    float4 o4 = make_float4(o[0], o[1], o[2], o[3]);
    if (writeOut) ((float4*)doutp)[idx] = o4;
    ((float4*)g_h)[idx] = o4;
    long base = (long)n * 128 + j4 * 4;
#pragma unroll
    for (int k = 0; k < 4; k++) {
        __nv_bfloat16 hh = __float2bfloat16(o[k]);
        g_hh[base + k] = hh;
        g_hl[base + k] = __float2bfloat16(o[k] - __bfloat162float(hh));
    }
}

// ---------------- launch -----------------------------------------------------
extern "C" void kernel_launch(void* const* d_in, const int* in_sizes, int n_in,
                              void* d_out, int out_size) {
    const float* x  = (const float*)d_in[0];
    const int*   ei = (const int*)d_in[1];     // int32 (JAX x64 disabled)
    const float* ea = (const float*)d_in[2];
    // d_in[3] = batch (unused)
    const float* W_embed = (const float*)d_in[4];
    const float* b_embed = (const float*)d_in[5];
    const float* W_snd   = (const float*)d_in[6];
    const float* b_snd   = (const float*)d_in[7];
    const float* W_rec   = (const float*)d_in[8];
    const float* b_rec   = (const float*)d_in[9];
    const float* W_ih    = (const float*)d_in[10];
    const float* b_ih    = (const float*)d_in[11];
    const float* W_hh    = (const float*)d_in[12];
    const float* b_hh    = (const float*)d_in[13];

    const int T = 256;
    const int rowBlocks = (NN + 127) / 128;   // 391

    // weight prep (split + transpose to K-major bf16 [Bh|Bh|Bl])
    wprep_kernel<<<(64 * 128 + T - 1) / T, T>>>(W_embed, 64, 128, OFF_WE);
    wprep_kernel<<<(128 * 128 + T - 1) / T, T>>>(W_snd, 128, 128, OFF_WS);
    wprep_kernel<<<(128 * 384 + T - 1) / T, T>>>(W_hh, 128, 384, OFF_WH);
    wprep_kernel<<<(256 * 256 + T - 1) / T, T>>>(W_rec, 256, 256, OFF_WR);
    wprep_kernel<<<(256 * 384 + T - 1) / T, T>>>(W_ih, 256, 384, OFF_WI);
    splitx_kernel<<<(NN * 64 + T - 1) / T, T>>>(x);

    // CSR build
    zero_cnt_kernel<<<(NN + T - 1) / T, T>>>();
    count_kernel<<<(EE + T - 1) / T, T>>>(ei);
    scan_kernel<<<1, 1024>>>();
    fill_kernel<<<(EE + T - 1) / T, T>>>(ei, ea);

    // embed: h = x @ W_embed + b_embed  (writes h fp32 + (hh,hl) pair)
    mma_gemm<<<dim3(rowBlocks, 1), T>>>(B_XH, B_XL, 64, -1, -1, 0,
                                        OFF_WE, b_embed,
                                        F_H, B_HH, B_HL, NN, 128, 0);

    for (int layer = 0; layer < 3; layer++) {
        // s = leaky(h @ W_snd + b)
        mma_gemm<<<dim3(rowBlocks, 1), T>>>(B_HH, B_HL, 128, -1, -1, 0,
                                            OFF_WS, b_snd,
                                            F_S, -1, -1, NN, 128, 1);
        // gh = h @ W_hh + b
        mma_gemm<<<dim3(rowBlocks, 3), T>>>(B_HH, B_HL, 128, -1, -1, 0,
                                            OFF_WH, b_hh,
                                            F_GH, -1, -1, NN, 384, 0);
        // agg = segment_mean via CSR gather -> (aggh, aggl)
        agg_kernel<<<(NN * 32 + T - 1) / T, T>>>();
        // m = leaky([agg, h] @ W_rec + b) -> (mh, ml)
        mma_gemm<<<dim3(rowBlocks, 2), T>>>(B_AGH, B_AGL, 128, B_HH, B_HL, 128,
                                            OFF_WR, b_rec,
                                            -1, B_MH, B_ML, NN, 256, 1);
        // gi = m @ W_ih + b
        mma_gemm<<<dim3(rowBlocks, 3), T>>>(B_MH, B_ML, 256, -1, -1, 0,
                                            OFF_WI, b_ih,
                                            F_GI, -1, -1, NN, 384, 0);
        // GRU update: writes h fp32 + (hh,hl); last layer also d_out
        gru_kernel<<<(NN * 32 + T - 1) / T, T>>>(
            (float*)d_out, layer == 2 ? 1 : 0);
    }
}

// round 17
// speedup vs baseline: 2.2613x; 1.0358x over previous
#include <cuda_runtime.h>
#include <cuda_bf16.h>
#include <cstdint>

// Problem constants
#define NN 50000
#define EE 800000

// ---------------- scratch (device globals; no allocation allowed) -----------
// fp32
__device__ float g_h  [(long long)NN * 128];
__device__ float g_s  [(long long)NN * 128];
__device__ float g_gi [(long long)NN * 384];
__device__ float g_gh [(long long)NN * 384];
__device__ float g_inv[NN];
__device__ int   g_cnt[NN];
__device__ int   g_start[NN + 1];
__device__ int   g_head[NN];
__device__ int   g_csr_row[EE];
__device__ float g_csr_ea[EE];
// bf16 split pairs (hi, lo) — 16B-aligned for uint4 access
__device__ __align__(16) __nv_bfloat16 g_xh [(long long)NN * 64];
__device__ __align__(16) __nv_bfloat16 g_xl [(long long)NN * 64];
__device__ __align__(16) __nv_bfloat16 g_hh [(long long)NN * 128];
__device__ __align__(16) __nv_bfloat16 g_hl [(long long)NN * 128];
__device__ __align__(16) __nv_bfloat16 g_agh[(long long)NN * 128];
__device__ __align__(16) __nv_bfloat16 g_agl[(long long)NN * 128];
__device__ __align__(16) __nv_bfloat16 g_mh [(long long)NN * 256];
__device__ __align__(16) __nv_bfloat16 g_ml [(long long)NN * 256];
// prepared weights: B' = [Bh; Bh; Bl], K-major [N][3K] bf16
__device__ __align__(16) __nv_bfloat16 g_wb[712704];

#define OFF_WE 0L
#define OFF_WS 24576L
#define OFF_WH 73728L
#define OFF_WR 221184L
#define OFF_WI 417792L

// f32 buffer ids
#define F_H  0
#define F_S  1
#define F_GI 2
#define F_GH 3
// bf16 buffer ids
#define B_XH 0
#define B_XL 1
#define B_HH 2
#define B_HL 3
#define B_AGH 4
#define B_AGL 5
#define B_MH 6
#define B_ML 7

__device__ __forceinline__ float* fbuf(int id) {
    switch (id) {
        case F_H:  return g_h;
        case F_S:  return g_s;
        case F_GI: return g_gi;
        case F_GH: return g_gh;
    }
    return nullptr;
}
__device__ __forceinline__ __nv_bfloat16* bbuf(int id) {
    switch (id) {
        case B_XH:  return g_xh;
        case B_XL:  return g_xl;
        case B_HH:  return g_hh;
        case B_HL:  return g_hl;
        case B_AGH: return g_agh;
        case B_AGL: return g_agl;
        case B_MH:  return g_mh;
        case B_ML:  return g_ml;
    }
    return nullptr;
}

__device__ __forceinline__ uint32_t smem_u32(const void* p) {
    uint32_t a;
    asm("{ .reg .u64 t; cvta.to.shared.u64 t, %1; cvt.u32.u64 %0, t; }"
        : "=r"(a) : "l"(p));
    return a;
}
__device__ __forceinline__ void cp16(uint32_t dst, const void* src) {
    asm volatile("cp.async.cg.shared.global [%0], [%1], 16;"
        :: "r"(dst), "l"(src));
}
#define CP_COMMIT() asm volatile("cp.async.commit_group;" ::: "memory")
#define CP_WAIT1()  asm volatile("cp.async.wait_group 1;" ::: "memory")

// ---------------- prep kernels ------------------------------------------------
// All 5 weight splits in ONE launch, segmented by flat index.
// Split+transpose W[K x N] fp32 -> B'[N][3K] bf16 = [Bh|Bh|Bl] along k'.
__global__ void wprep_all_kernel(const float* __restrict__ W0,  // embed 64x128
                                 const float* __restrict__ W1,  // snd 128x128
                                 const float* __restrict__ W2,  // hh 128x384
                                 const float* __restrict__ W3,  // rec 256x256
                                 const float* __restrict__ W4)  // ih 256x384
{
    int idx = blockIdx.x * blockDim.x + threadIdx.x;
    const float* W; int K, N; long off;
    if      (idx <   8192) { W = W0; K = 64;  N = 128; off = OFF_WE; }
    else if (idx <  24576) { idx -=   8192; W = W1; K = 128; N = 128; off = OFF_WS; }
    else if (idx <  73728) { idx -=  24576; W = W2; K = 128; N = 384; off = OFF_WH; }
    else if (idx < 139264) { idx -=  73728; W = W3; K = 256; N = 256; off = OFF_WR; }
    else if (idx < 237568) { idx -= 139264; W = W4; K = 256; N = 384; off = OFF_WI; }
    else return;
    int k = idx / N, n = idx % N;
    float w = W[idx];
    __nv_bfloat16 wh = __float2bfloat16(w);
    __nv_bfloat16 wl = __float2bfloat16(w - __bfloat162float(wh));
    long base = off + (long)n * 3 * K;
    g_wb[base + k]         = wh;
    g_wb[base + K + k]     = wh;
    g_wb[base + 2 * K + k] = wl;
}

__global__ void splitx_kernel(const float* __restrict__ x) {
    long i = (long)blockIdx.x * blockDim.x + threadIdx.x;
    if (i >= (long)NN * 64) return;
    float v = x[i];
    __nv_bfloat16 h = __float2bfloat16(v);
    g_xh[i] = h;
    g_xl[i] = __float2bfloat16(v - __bfloat162float(h));
}

// ---------------- degree / CSR build -----------------------------------------
__global__ void zero_cnt_kernel() {
    int i = blockIdx.x * blockDim.x + threadIdx.x;
    if (i < NN) g_cnt[i] = 0;
}
__global__ void count_kernel(const int* __restrict__ ei) {
    int e = blockIdx.x * blockDim.x + threadIdx.x;
    if (e < EE) {
        unsigned c = (unsigned)ei[EE + e];
        if (c < NN) atomicAdd(&g_cnt[c], 1);
    }
}
__global__ void scan_kernel() {
    __shared__ int ssum[1024];
    const int CH = (NN + 1023) / 1024;
    int t = threadIdx.x;
    int beg = t * CH;
    int end = beg + CH; if (end > NN) end = NN;
    int s = 0;
    for (int i = beg; i < end; i++) s += g_cnt[i];
    ssum[t] = s;
    __syncthreads();
    for (int off = 1; off < 1024; off <<= 1) {
        int v = (t >= off) ? ssum[t - off] : 0;
        __syncthreads();
        ssum[t] += v;
        __syncthreads();
    }
    int run = ssum[t] - s;
    for (int i = beg; i < end; i++) {
        int c = g_cnt[i];
        g_start[i] = run;
        g_head[i]  = run;
        g_inv[i]   = 1.0f / (float)(c > 0 ? c : 1);
        run += c;
    }
    if (t == 1023) g_start[NN] = ssum[1023];
}
__global__ void fill_kernel(const int* __restrict__ ei,
                            const float* __restrict__ ea) {
    int e = blockIdx.x * blockDim.x + threadIdx.x;
    if (e >= EE) return;
    unsigned r = (unsigned)ei[e];
    unsigned c = (unsigned)ei[EE + e];
    if (c < NN) {
        int p = atomicAdd(&g_head[c], 1);
        g_csr_row[p] = (r < NN) ? (int)r : 0;
        g_csr_ea[p]  = ea[e];
    }
}

// ---------------- aggregation: CSR gather, index-prefetch pipeline -----------
__global__ void agg_kernel() {
    int gid  = blockIdx.x * blockDim.x + threadIdx.x;
    int n    = gid >> 5;
    int lane = gid & 31;
    if (n >= NN) return;
    int beg = g_start[n];
    int end = g_start[n + 1];
    float4 acc = make_float4(0.f, 0.f, 0.f, 0.f);
    int e = beg;
    int r0 = 0, r1 = 0, r2 = 0, r3 = 0;
    float a0 = 0.f, a1 = 0.f, a2 = 0.f, a3 = 0.f;
    bool have = (e + 3 < end);
    if (have) {
        r0 = g_csr_row[e];     r1 = g_csr_row[e + 1];
        r2 = g_csr_row[e + 2]; r3 = g_csr_row[e + 3];
        a0 = g_csr_ea[e];      a1 = g_csr_ea[e + 1];
        a2 = g_csr_ea[e + 2];  a3 = g_csr_ea[e + 3];
    }
    while (have) {
        // issue gathers for current group
        float4 v0 = ((const float4*)(g_s + (long long)r0 * 128))[lane];
        float4 v1 = ((const float4*)(g_s + (long long)r1 * 128))[lane];
        float4 v2 = ((const float4*)(g_s + (long long)r2 * 128))[lane];
        float4 v3 = ((const float4*)(g_s + (long long)r3 * 128))[lane];
        // prefetch next group's indices while gathers are in flight
        int en = e + 4;
        bool haveN = (en + 3 < end);
        int nr0 = 0, nr1 = 0, nr2 = 0, nr3 = 0;
        float na0 = 0.f, na1 = 0.f, na2 = 0.f, na3 = 0.f;
        if (haveN) {
            nr0 = g_csr_row[en];     nr1 = g_csr_row[en + 1];
            nr2 = g_csr_row[en + 2]; nr3 = g_csr_row[en + 3];
            na0 = g_csr_ea[en];      na1 = g_csr_ea[en + 1];
            na2 = g_csr_ea[en + 2];  na3 = g_csr_ea[en + 3];
        }
        acc.x += v0.x * a0 + v1.x * a1 + v2.x * a2 + v3.x * a3;
        acc.y += v0.y * a0 + v1.y * a1 + v2.y * a2 + v3.y * a3;
        acc.z += v0.z * a0 + v1.z * a1 + v2.z * a2 + v3.z * a3;
        acc.w += v0.w * a0 + v1.w * a1 + v2.w * a2 + v3.w * a3;
        e = en;
        r0 = nr0; r1 = nr1; r2 = nr2; r3 = nr3;
        a0 = na0; a1 = na1; a2 = na2; a3 = na3;
        have = haveN;
    }
    for (; e < end; e++) {
        int   rr = g_csr_row[e];
        float aa = g_csr_ea[e];
        float4 v0 = ((const float4*)(g_s + (long long)rr * 128))[lane];
        acc.x += v0.x * aa; acc.y += v0.y * aa;
        acc.z += v0.z * aa; acc.w += v0.w * aa;
    }
    float iv = g_inv[n];
    float vals[4] = {acc.x * iv, acc.y * iv, acc.z * iv, acc.w * iv};
    long base = (long)n * 128 + lane * 4;
#pragma unroll
    for (int k = 0; k < 4; k++) {
        __nv_bfloat16 h = __float2bfloat16(vals[k]);
        g_agh[base + k] = h;
        g_agl[base + k] = __float2bfloat16(vals[k] - __bfloat162float(h));
    }
}

// ---------------- bf16-split warp-MMA GEMM, cp.async 3-stage pipeline --------
// C = act( concat(A0, A1)[M x (K0+K1)] @ W' + bias ); dual-output splitY:
// blockIdx.y < splitY -> set 1 (wOff, bias, outF32/outH/outL, Nc, act)
// else                 -> set 2 (wOff2, bias2, outF32b, Nc2, act2), yy -= splitY
// A as bf16 split pairs, W pre-split in g_wb as [Nc][3K'] K-major bf16.
// CTA 256 thr = 8 warps (4m x 2n), tile 128x128; K' chunks of 32.
// 16B-slot XOR swizzle: part' = part ^ ((row>>1)&3).
#define NSTAGE 3

__global__ __launch_bounds__(256)
void mma_gemm(int a0h, int a0l, int K0, int a1h, int a1l, int K1,
              long wOff, const float* __restrict__ bias,
              int outF32, int outH, int outL,
              int M, int Nc, int act, int splitY,
              long wOff2, const float* __restrict__ bias2,
              int outF32b, int Nc2, int act2) {
    __shared__ __align__(16) unsigned char sm[NSTAGE][16384];  // [A 8K | B 8K]

    const int t    = threadIdx.x;
    const int lane = t & 31;
    const int wid  = t >> 5;
    const int warpM = wid >> 1;          // 0..3
    const int warpN = wid & 1;           // 0..1
    const int m0 = blockIdx.x * 128;

    int yy = blockIdx.y;
    long wO = wOff; const float* bp = bias;
    int oF = outF32, oH = outH, oL = outL, NcS = Nc, actS = act;
    if (splitY >= 0 && (int)blockIdx.y >= splitY) {
        yy -= splitY;
        wO = wOff2; bp = bias2;
        oF = outF32b; oH = -1; oL = -1; NcS = Nc2; actS = act2;
    }
    const int n0 = yy * 128;

    const __nv_bfloat16* A0h = bbuf(a0h);
    const __nv_bfloat16* A0l = bbuf(a0l);
    const __nv_bfloat16* A1h = (a1h >= 0) ? bbuf(a1h) : nullptr;
    const __nv_bfloat16* A1l = (a1l >= 0) ? bbuf(a1l) : nullptr;
    const __nv_bfloat16* Bw  = g_wb + wO;

    const int Ksum  = K0 + K1;
    const int Kp    = 3 * Ksum;
    const int niter = Kp / 32;

    const uint32_t sbase = smem_u32(sm);

    float acc[2][8][4];
#pragma unroll
    for (int i = 0; i < 2; i++)
#pragma unroll
        for (int j = 0; j < 8; j++)
#pragma unroll
            for (int k = 0; k < 4; k++) acc[i][j][k] = 0.f;

    auto issue = [&](int ch) {
        int kp  = ch * 32;
        int seg = kp / Ksum;
        int kg  = kp - seg * Ksum;
        const __nv_bfloat16* As;
        int pitch;
        if (kg < K0) { As = (seg == 1) ? A0l : A0h; pitch = K0; }
        else         { As = (seg == 1) ? A1l : A1h; pitch = K1; kg -= K0; }
        uint32_t stA = sbase + (ch % NSTAGE) * 16384;
        uint32_t stB = stA + 8192;
#pragma unroll
        for (int q = 0; q < 2; q++) {
            int idx  = t + q * 256;       // [0,512)
            int row  = idx >> 2;          // 0..127
            int part = idx & 3;           // 16B slot within 64B row
            uint32_t sw = (uint32_t)((part ^ ((row >> 1) & 3)) * 16);
            int grow = m0 + row; if (grow >= M) grow = M - 1;   // clamp (discarded)
            cp16(stA + row * 64 + sw,
                 As + (long)grow * pitch + kg + part * 8);
            cp16(stB + row * 64 + sw,
                 Bw + (long)(n0 + row) * Kp + kp + part * 8);
        }
    };

    auto compute = [&](int slot) {
        uint32_t stA = sbase + slot * 16384;
        uint32_t stB = stA + 8192;
#pragma unroll
        for (int ks = 0; ks < 2; ks++) {
            uint32_t af[2][4];
#pragma unroll
            for (int mf = 0; mf < 2; mf++) {
                int r = warpM * 32 + mf * 16 + (lane & 15);
                int cpart = ks * 2 + ((lane >> 4) & 1);
                uint32_t ad = stA + (uint32_t)(r * 64 +
                              ((cpart ^ ((r >> 1) & 3)) * 16));
                asm volatile(
                    "ldmatrix.sync.aligned.m8n8.x4.shared.b16 {%0,%1,%2,%3}, [%4];"
                    : "=r"(af[mf][0]), "=r"(af[mf][1]),
                      "=r"(af[mf][2]), "=r"(af[mf][3]) : "r"(ad));
            }
            uint32_t bf[8][2];
#pragma unroll
            for (int np = 0; np < 4; np++) {
                int n = warpN * 64 + np * 16 + ((lane >> 4) & 1) * 8 + (lane & 7);
                int cpart = ks * 2 + ((lane >> 3) & 1);
                uint32_t bd = stB + (uint32_t)(n * 64 +
                              ((cpart ^ ((n >> 1) & 3)) * 16));
                asm volatile(
                    "ldmatrix.sync.aligned.m8n8.x4.shared.b16 {%0,%1,%2,%3}, [%4];"
                    : "=r"(bf[2 * np][0]), "=r"(bf[2 * np][1]),
                      "=r"(bf[2 * np + 1][0]), "=r"(bf[2 * np + 1][1]) : "r"(bd));
            }
#pragma unroll
            for (int mf = 0; mf < 2; mf++)
#pragma unroll
                for (int nf = 0; nf < 8; nf++) {
                    asm volatile(
                        "mma.sync.aligned.m16n8k16.row.col.f32.bf16.bf16.f32 "
                        "{%0,%1,%2,%3}, {%4,%5,%6,%7}, {%8,%9}, {%0,%1,%2,%3};"
                        : "+f"(acc[mf][nf][0]), "+f"(acc[mf][nf][1]),
                          "+f"(acc[mf][nf][2]), "+f"(acc[mf][nf][3])
                        : "r"(af[mf][0]), "r"(af[mf][1]),
                          "r"(af[mf][2]), "r"(af[mf][3]),
                          "r"(bf[nf][0]), "r"(bf[nf][1]));
                }
        }
    };

    // prologue: stages 0..NSTAGE-2
#pragma unroll
    for (int st = 0; st < NSTAGE - 1; st++) {
        if (st < niter) issue(st);
        CP_COMMIT();
    }
    for (int it = 0; it < niter; it++) {
        CP_WAIT1();          // group 'it' complete (in-order; empty commits pad)
        __syncthreads();     // all warps see stage, done computing stage it-1
        int nst = it + NSTAGE - 1;
        if (nst < niter) issue(nst);
        CP_COMMIT();
        compute(it % NSTAGE);
    }

    // --- epilogue: bias + act + fp32 and/or bf16-split stores
    float* Cf = (oF >= 0) ? fbuf(oF) : nullptr;
    __nv_bfloat16* Ch = (oH >= 0) ? bbuf(oH) : nullptr;
    __nv_bfloat16* Cl = (oH >= 0) ? bbuf(oL) : nullptr;

#pragma unroll
    for (int mf = 0; mf < 2; mf++) {
#pragma unroll
        for (int nf = 0; nf < 8; nf++) {
            int col = n0 + warpN * 64 + nf * 8 + 2 * (lane & 3);
            float bb0 = bp[col], bb1 = bp[col + 1];
#pragma unroll
            for (int half = 0; half < 2; half++) {
                int row = m0 + warpM * 32 + mf * 16 + (lane >> 2) + half * 8;
                if (row >= M) continue;
                float v0 = acc[mf][nf][2 * half + 0] + bb0;
                float v1 = acc[mf][nf][2 * half + 1] + bb1;
                if (actS == 1) {
                    v0 = v0 > 0.f ? v0 : 0.01f * v0;
                    v1 = v1 > 0.f ? v1 : 0.01f * v1;
                }
                long o = (long)row * NcS + col;
                if (Cf) *(float2*)(Cf + o) = make_float2(v0, v1);
                if (Ch) {
                    __nv_bfloat16 h0 = __float2bfloat16(v0);
                    __nv_bfloat16 h1 = __float2bfloat16(v1);
                    __nv_bfloat162 hv; hv.x = h0; hv.y = h1;
                    *(__nv_bfloat162*)(Ch + o) = hv;
                    __nv_bfloat162 lv;
                    lv.x = __float2bfloat16(v0 - __bfloat162float(h0));
                    lv.y = __float2bfloat16(v1 - __bfloat162float(h1));
                    *(__nv_bfloat162*)(Cl + o) = lv;
                }
            }
        }
    }
}

// ---------------- GRU elementwise update + bf16 split out --------------------
__global__ void gru_kernel(float* __restrict__ doutp, int writeOut) {
    int idx = blockIdx.x * blockDim.x + threadIdx.x;   // over NN*32
    if (idx >= NN * 32) return;
    int n  = idx >> 5;
    int j4 = idx & 31;
    const float4* gi4 = (const float4*)(g_gi + (long long)n * 384);
    const float4* gh4 = (const float4*)(g_gh + (long long)n * 384);
    float4 ir  = gi4[j4],      hr = gh4[j4];
    float4 iz  = gi4[32 + j4], hz = gh4[32 + j4];
    float4 inn = gi4[64 + j4], hn = gh4[64 + j4];
    float4 h   = ((const float4*)(g_h + (long long)n * 128))[j4];
    float o[4];
    float irv[4] = {ir.x, ir.y, ir.z, ir.w};
    float hrv[4] = {hr.x, hr.y, hr.z, hr.w};
    float izv[4] = {iz.x, iz.y, iz.z, iz.w};
    float hzv[4] = {hz.x, hz.y, hz.z, hz.w};
    float inv_[4] = {inn.x, inn.y, inn.z, inn.w};
    float hnv[4] = {hn.x, hn.y, hn.z, hn.w};
    float hv[4]  = {h.x, h.y, h.z, h.w};
#pragma unroll
    for (int k = 0; k < 4; k++) {
        float r = 1.f / (1.f + __expf(-(irv[k] + hrv[k])));
        float z = 1.f / (1.f + __expf(-(izv[k] + hzv[k])));
        float nv = tanhf(inv_[k] + r * hnv[k]);
        o[k] = (1.f - z) * nv + z * hv[k];
    }
    float4 o4 = make_float4(o[0], o[1], o[2], o[3]);
    if (writeOut) {
        ((float4*)doutp)[idx] = o4;   // last layer: d_out only, skip dead stores
    } else {
        ((float4*)g_h)[idx] = o4;
        long base = (long)n * 128 + j4 * 4;
#pragma unroll
        for (int k = 0; k < 4; k++) {
            __nv_bfloat16 hh = __float2bfloat16(o[k]);
            g_hh[base + k] = hh;
            g_hl[base + k] = __float2bfloat16(o[k] - __bfloat162float(hh));
        }
    }
}

// ---------------- launch -----------------------------------------------------
extern "C" void kernel_launch(void* const* d_in, const int* in_sizes, int n_in,
                              void* d_out, int out_size) {
    const float* x  = (const float*)d_in[0];
    const int*   ei = (const int*)d_in[1];     // int32 (JAX x64 disabled)
    const float* ea = (const float*)d_in[2];
    // d_in[3] = batch (unused)
    const float* W_embed = (const float*)d_in[4];
    const float* b_embed = (const float*)d_in[5];
    const float* W_snd   = (const float*)d_in[6];
    const float* b_snd   = (const float*)d_in[7];
    const float* W_rec   = (const float*)d_in[8];
    const float* b_rec   = (const float*)d_in[9];
    const float* W_ih    = (const float*)d_in[10];
    const float* b_ih    = (const float*)d_in[11];
    const float* W_hh    = (const float*)d_in[12];
    const float* b_hh    = (const float*)d_in[13];

    const int T = 256;
    const int rowBlocks = (NN + 127) / 128;   // 391

    // weight prep: ONE launch for all 5 splits
    wprep_all_kernel<<<(237568 + T - 1) / T, T>>>(W_embed, W_snd, W_hh,
                                                  W_rec, W_ih);
    splitx_kernel<<<(NN * 64 + T - 1) / T, T>>>(x);

    // CSR build
    zero_cnt_kernel<<<(NN + T - 1) / T, T>>>();
    count_kernel<<<(EE + T - 1) / T, T>>>(ei);
    scan_kernel<<<1, 1024>>>();
    fill_kernel<<<(EE + T - 1) / T, T>>>(ei, ea);

    // embed: h = x @ W_embed + b_embed  (writes h fp32 + (hh,hl) pair)
    mma_gemm<<<dim3(rowBlocks, 1), T>>>(B_XH, B_XL, 64, -1, -1, 0,
                                        OFF_WE, b_embed,
                                        F_H, B_HH, B_HL, NN, 128, 0, -1,
                                        0L, nullptr, -1, 0, 0);

    for (int layer = 0; layer < 3; layer++) {
        // fused: s = leaky(h@W_snd+b) [y=0]  and  gh = h@W_hh+b [y=1..3]
        mma_gemm<<<dim3(rowBlocks, 4), T>>>(B_HH, B_HL, 128, -1, -1, 0,
                                            OFF_WS, b_snd,
                                            F_S, -1, -1, NN, 128, 1, 1,
                                            OFF_WH, b_hh, F_GH, 384, 0);
        // agg = segment_mean via CSR gather -> (aggh, aggl)
        agg_kernel<<<(NN * 32 + T - 1) / T, T>>>();
        // m = leaky([agg, h] @ W_rec + b) -> (mh, ml)
        mma_gemm<<<dim3(rowBlocks, 2), T>>>(B_AGH, B_AGL, 128, B_HH, B_HL, 128,
                                            OFF_WR, b_rec,
                                            -1, B_MH, B_ML, NN, 256, 1, -1,
                                            0L, nullptr, -1, 0, 0);
        // gi = m @ W_ih + b
        mma_gemm<<<dim3(rowBlocks, 3), T>>>(B_MH, B_ML, 256, -1, -1, 0,
                                            OFF_WI, b_ih,
                                            F_GI, -1, -1, NN, 384, 0, -1,
                                            0L, nullptr, -1, 0, 0);
        // GRU update: layers 0/1 write h + (hh,hl); last layer writes d_out
        gru_kernel<<<(NN * 32 + T - 1) / T, T>>>(
            (float*)d_out, layer == 2 ? 1 : 0);
    }
}